// round 12
// baseline (speedup 1.0000x reference)
#include <cuda_runtime.h>
#include <cuda_fp16.h>
#include <math.h>
#include <stdint.h>

#define S_LEN   2048
#define BATCH   2
#define DMODEL  1024
#define NHEAD   16
#define NKV     4
#define HEADDIM 64
#define NTOK    4096            // S_LEN * BATCH
#define DFF     4096            // 4 * DMODEL
#define QKVN    1536            // 1024 + 256 + 256
#define EPS_F   1e-5f
#define QK_SCALE 0.03125f       // D^-0.5 = 1/32

// fp16 GEMM smem: 4 stages, tiles [128 rows][40 halfs] (stride 80B)
#define GF_TILE_BYTES 10240     // 128*80
#define GF_STAGES 4
#define GF_SMEM_BYTES (2 * GF_STAGES * GF_TILE_BYTES)   // 81920

// ---------------- scratch (__device__ globals; no allocation allowed) ----------------
__device__ __half g_h   [NTOK * DMODEL];
__device__ __half g_wqkv[QKVN * DMODEL];      // transposed [N,K]
__device__ float  g_bqkv[QKVN];
__device__ __half g_qkv [NTOK * QKVN];
__device__ __half g_q   [BATCH * NHEAD * S_LEN * HEADDIM];
__device__ __half g_k   [BATCH * NKV   * S_LEN * HEADDIM];
__device__ __half g_v   [BATCH * NKV   * S_LEN * HEADDIM];
__device__ __half g_attn[NTOK * DMODEL];
__device__ float  g_x1  [NTOK * DMODEL];
__device__ __half g_h2  [NTOK * DMODEL];
__device__ __half g_mid [NTOK * DFF];
__device__ __half g_wor [DMODEL * DMODEL];    // transposed
__device__ __half g_w1r [DFF * DMODEL];       // transposed
__device__ __half g_w2r [DMODEL * DFF];       // transposed

__device__ __forceinline__ void cp16s(uint32_t daddr, const void* src) {
    asm volatile("cp.async.ca.shared.global [%0], [%1], 16;" :: "r"(daddr), "l"(src));
}
__device__ __forceinline__ unsigned packh2(float a, float b) {
    __half2 h = __floats2half2_rn(a, b);
    return *(unsigned*)&h;
}

// ---------------- pack wq|wk|wv transposed: Wt[c][k] fp16 ----------------
__global__ __launch_bounds__(256)
void pack_wqkv_t_kernel(const float* __restrict__ wq, const float* __restrict__ wk,
                        const float* __restrict__ wv, __half* __restrict__ Wt)
{
    __shared__ float t[32][33];
    int bx = blockIdx.x * 32;   // c base
    int by = blockIdx.y * 32;   // k base
    int tx = threadIdx.x & 31;
    int ty = threadIdx.x >> 5;
    #pragma unroll
    for (int j = 0; j < 4; j++) {
        int k = by + ty + 8 * j;
        int c = bx + tx;
        float v;
        if (c < 1024)       v = wq[(size_t)k * 1024 + c];
        else if (c < 1280)  v = wk[(size_t)k * 256 + (c - 1024)];
        else                v = wv[(size_t)k * 256 + (c - 1280)];
        t[ty + 8 * j][tx] = v;
    }
    __syncthreads();
    #pragma unroll
    for (int j = 0; j < 4; j++) {
        int c = bx + ty + 8 * j;
        Wt[(size_t)c * DMODEL + by + tx] = __float2half_rn(t[tx][ty + 8 * j]);
    }
}

// ---------------- fp16 transpose: dst[C][R] = half(src[R][C]) ----------------
__global__ __launch_bounds__(256)
void transpose_h_kernel(const float* __restrict__ src, __half* __restrict__ dst,
                        int R, int C)
{
    __shared__ float t[32][33];
    int bx = blockIdx.x * 32;   // C base
    int by = blockIdx.y * 32;   // R base
    int tx = threadIdx.x & 31;
    int ty = threadIdx.x >> 5;
    #pragma unroll
    for (int j = 0; j < 4; j++)
        t[ty + 8 * j][tx] = src[(size_t)(by + ty + 8 * j) * C + bx + tx];
    __syncthreads();
    #pragma unroll
    for (int j = 0; j < 4; j++)
        dst[(size_t)(bx + ty + 8 * j) * R + by + tx] = __float2half_rn(t[tx][ty + 8 * j]);
}

__global__ void packbias_kernel(const float* __restrict__ bq, const float* __restrict__ bk,
                                const float* __restrict__ bv, float* __restrict__ bias)
{
    int i = blockIdx.x * 256 + threadIdx.x;
    if (i < QKVN)
        bias[i] = (i < 1024) ? bq[i] : (i < 1280 ? bk[i - 1024] : bv[i - 1280]);
}

// ---------------- RMSNorm over D=1024, fp16 output ----------------
__global__ __launch_bounds__(256)
void rmsnorm_kernel(const float* __restrict__ x, const float* __restrict__ w,
                    __half* __restrict__ y)
{
    int row = blockIdx.x;
    int i = threadIdx.x;
    const float* xr = x + (size_t)row * DMODEL;
    float4 xv = *(const float4*)(xr + i * 4);
    float ss = xv.x * xv.x + xv.y * xv.y + xv.z * xv.z + xv.w * xv.w;
    #pragma unroll
    for (int off = 16; off; off >>= 1) ss += __shfl_xor_sync(0xffffffffu, ss, off);
    __shared__ float red[8];
    __shared__ float s_sc;
    if ((i & 31) == 0) red[i >> 5] = ss;
    __syncthreads();
    if (i == 0) {
        float tot = 0.f;
        #pragma unroll
        for (int kk = 0; kk < 8; kk++) tot += red[kk];
        s_sc = rsqrtf(tot * (1.0f / DMODEL) + EPS_F);
    }
    __syncthreads();
    float sc = s_sc;
    float4 wv = *(const float4*)(w + i * 4);
    uint2 u;
    u.x = packh2(xv.x * sc * wv.x, xv.y * sc * wv.y);
    u.y = packh2(xv.z * sc * wv.z, xv.w * sc * wv.w);
    *(uint2*)(y + (size_t)row * DMODEL + i * 4) = u;
}

// ---------------- per-head QK RMSNorm + RoPE + relayout (fp16 in/out) ----------------
__global__ __launch_bounds__(256)
void qkrope_kernel(const __half* __restrict__ qkv, const float* __restrict__ qn_w,
                   const float* __restrict__ kn_w, __half* __restrict__ Qo,
                   __half* __restrict__ Ko, __half* __restrict__ Vo)
{
    int t = blockIdx.x;            // token = s*BATCH + b
    int ty = threadIdx.y;          // 0..3
    int slot = blockIdx.y * 4 + ty;
    int i = threadIdx.x;           // 0..63
    int s = t / BATCH, b = t % BATCH;
    __shared__ float buf[4][64];
    __shared__ float red[4][2];

    if (slot >= 20) {   // V: pure relayout (whole block is V)
        int vh = slot - 20;
        Vo[((size_t)(b * NKV + vh) * S_LEN + s) * 64 + i] =
            qkv[(size_t)t * QKVN + 1280 + vh * 64 + i];
        return;
    }

    bool is_q = (slot < 16);
    int col = is_q ? (slot * 64 + i) : (1024 + (slot - 16) * 64 + i);
    float v = __half2float(qkv[(size_t)t * QKVN + col]);
    float ss = v * v;
    #pragma unroll
    for (int off = 16; off; off >>= 1) ss += __shfl_xor_sync(0xffffffffu, ss, off);
    if ((i & 31) == 0) red[ty][i >> 5] = ss;
    __syncthreads();
    float tot = red[ty][0] + red[ty][1];
    float sc = rsqrtf(tot * (1.0f / 64.0f) + EPS_F);
    const float* w = is_q ? qn_w : kn_w;
    float nv = v * sc * w[i];
    buf[ty][i] = nv;
    __syncthreads();
    float rot = (i < 32) ? -buf[ty][i + 32] : buf[ty][i - 32];
    int j = i & 31;
    float invf = exp2f(-(float)j * (13.287712379549449f / 32.0f));
    float ang = (float)s * invf;
    float sn, cs;
    sincosf(ang, &sn, &cs);
    float outv = nv * cs + rot * sn;
    if (is_q) {
        outv *= QK_SCALE;
        Qo[((size_t)(b * NHEAD + slot) * S_LEN + s) * 64 + i] = __float2half_rn(outv);
    } else {
        Ko[((size_t)(b * NKV + (slot - 16)) * S_LEN + s) * 64 + i] = __float2half_rn(outv);
    }
}

// ---------------- fp16 GEMM stage loader: 8 cp.async per thread ----------------
__device__ __forceinline__ void gf_load(uint32_t sA, uint32_t sB,
                                        const __half* Ag, const __half* Bg,
                                        int K, int k0, int tid)
{
    int r0 = tid >> 2;             // 0..31
    int ch = (tid & 3) << 3;       // half offset in row: 0,8,16,24
    #pragma unroll
    for (int j = 0; j < 4; j++) {
        int r = r0 + 32 * j;
        uint32_t so = (uint32_t)(r * 80 + ch * 2);
        cp16s(sA + so, Ag + (size_t)r * K + k0 + ch);
        cp16s(sB + so, Bg + (size_t)r * K + k0 + ch);
    }
    asm volatile("cp.async.commit_group;" ::: "memory");
}

// ---------------- fp16 GEMM ----------------
// EPI: 0 = +bias fp32 out, 1 = gelu(+bias) fp16 out, 2 = +bias+residual fp32 out,
//      3 = +bias fp16 out
template<int EPI>
__global__ __launch_bounds__(128)
void gemm_f16_kernel(const __half* __restrict__ A, const __half* __restrict__ Bt,
                     const float* __restrict__ bias, const float* __restrict__ res,
                     void* __restrict__ Cout, int M, int N, int K)
{
    extern __shared__ char smc[];
    uint32_t smem_base;
    asm("{ .reg .u64 t; cvta.to.shared.u64 t, %1; cvt.u32.u64 %0, t; }"
        : "=r"(smem_base) : "l"(smc));

    int tid  = threadIdx.x;
    int wid  = tid >> 5, lane = tid & 31;
    int g    = lane >> 2;
    int q    = lane & 3;
    int wm   = (wid >> 1) * 64;
    int wn   = (wid & 1) * 64;

    int row0 = blockIdx.y * 128;
    int col0 = blockIdx.x * 128;
    const __half* Ag = A  + (size_t)row0 * K;
    const __half* Bg = Bt + (size_t)col0 * K;

    float acc[4][8][4];
    #pragma unroll
    for (int mt = 0; mt < 4; mt++)
        #pragma unroll
        for (int nt = 0; nt < 8; nt++)
            #pragma unroll
            for (int r = 0; r < 4; r++) acc[mt][nt][r] = 0.f;

    const int KT = K >> 5;

    #pragma unroll
    for (int st = 0; st < 3; st++)
        gf_load(smem_base + st * GF_TILE_BYTES,
                smem_base + (GF_STAGES + st) * GF_TILE_BYTES,
                Ag, Bg, K, st * 32, tid);

    for (int kt = 0; kt < KT; kt++) {
        asm volatile("cp.async.wait_group 2;" ::: "memory");
        __syncthreads();

        if (kt + 3 < KT) {
            int st = (kt + 3) & 3;
            gf_load(smem_base + st * GF_TILE_BYTES,
                    smem_base + (GF_STAGES + st) * GF_TILE_BYTES,
                    Ag, Bg, K, (kt + 3) * 32, tid);
        }

        int st = kt & 3;
        const __half* As = (const __half*)(smc + st * GF_TILE_BYTES);
        const __half* Bs = (const __half*)(smc + (GF_STAGES + st) * GF_TILE_BYTES);

        #pragma unroll
        for (int kk = 0; kk < 32; kk += 16) {
            unsigned af[4][4];
            #pragma unroll
            for (int mt = 0; mt < 4; mt++) {
                int r = wm + mt * 16 + g;
                af[mt][0] = *(const unsigned*)(As + r * 40 + kk + 2 * q);
                af[mt][1] = *(const unsigned*)(As + (r + 8) * 40 + kk + 2 * q);
                af[mt][2] = *(const unsigned*)(As + r * 40 + kk + 2 * q + 8);
                af[mt][3] = *(const unsigned*)(As + (r + 8) * 40 + kk + 2 * q + 8);
            }
            unsigned bf[8][2];
            #pragma unroll
            for (int nt = 0; nt < 8; nt++) {
                int c = wn + nt * 8 + g;
                bf[nt][0] = *(const unsigned*)(Bs + c * 40 + kk + 2 * q);
                bf[nt][1] = *(const unsigned*)(Bs + c * 40 + kk + 2 * q + 8);
            }
            #pragma unroll
            for (int mt = 0; mt < 4; mt++)
                #pragma unroll
                for (int nt = 0; nt < 8; nt++) {
                    asm volatile(
                        "mma.sync.aligned.m16n8k16.row.col.f32.f16.f16.f32 "
                        "{%0,%1,%2,%3}, {%4,%5,%6,%7}, {%8,%9}, {%0,%1,%2,%3};"
                        : "+f"(acc[mt][nt][0]), "+f"(acc[mt][nt][1]),
                          "+f"(acc[mt][nt][2]), "+f"(acc[mt][nt][3])
                        : "r"(af[mt][0]), "r"(af[mt][1]), "r"(af[mt][2]), "r"(af[mt][3]),
                          "r"(bf[nt][0]), "r"(bf[nt][1]));
                }
        }
    }

    #pragma unroll
    for (int mt = 0; mt < 4; mt++) {
        int r = row0 + wm + mt * 16 + g;
        #pragma unroll
        for (int nt = 0; nt < 8; nt++) {
            int c = col0 + wn + nt * 8 + 2 * q;
            float bv0 = bias[c], bv1 = bias[c + 1];
            float v00 = acc[mt][nt][0] + bv0;
            float v01 = acc[mt][nt][1] + bv1;
            float v10 = acc[mt][nt][2] + bv0;
            float v11 = acc[mt][nt][3] + bv1;
            if (EPI == 1) {
                v00 = 0.5f * v00 * (1.0f + erff(v00 * 0.70710678118654752f));
                v01 = 0.5f * v01 * (1.0f + erff(v01 * 0.70710678118654752f));
                v10 = 0.5f * v10 * (1.0f + erff(v10 * 0.70710678118654752f));
                v11 = 0.5f * v11 * (1.0f + erff(v11 * 0.70710678118654752f));
            }
            if (EPI == 1 || EPI == 3) {
                __half* C = (__half*)Cout;
                *(unsigned*)(C + (size_t)r * N + c)       = packh2(v00, v01);
                *(unsigned*)(C + (size_t)(r + 8) * N + c) = packh2(v10, v11);
            } else {
                float* C = (float*)Cout;
                if (EPI == 2) {
                    float2 r0 = *(const float2*)(res + (size_t)r * N + c);
                    float2 r1 = *(const float2*)(res + (size_t)(r + 8) * N + c);
                    v00 += r0.x; v01 += r0.y;
                    v10 += r1.x; v11 += r1.y;
                }
                *(float2*)(C + (size_t)r * N + c)       = make_float2(v00, v01);
                *(float2*)(C + (size_t)(r + 8) * N + c) = make_float2(v10, v11);
            }
        }
    }
}

// ---------------- fp16 flash attention, cp.async double-buffered K/V ----------------
// BQ=64, BKV=64, 4 warps, causal, GQA. Q fragments hoisted (loop-invariant).
__global__ __launch_bounds__(128)
void attn_f16_kernel(const __half* __restrict__ Q, const __half* __restrict__ K,
                     const __half* __restrict__ V, __half* __restrict__ O)
{
    __shared__ __half Qs[64][72];
    __shared__ __half Ks[2][64][72];
    __shared__ __half Vs[2][64][72];

    int tid  = threadIdx.x;
    int wid  = tid >> 5, lane = tid & 31;
    int g    = lane >> 2;
    int q    = lane & 3;
    int qt   = blockIdx.x;
    int bh   = blockIdx.y;
    int b    = bh >> 4;
    int h    = bh & 15;
    int kvh  = h >> 2;
    int q0   = qt * 64;

    const __half* Qb = Q + (size_t)(b * NHEAD + h)  * S_LEN * 64 + (size_t)q0 * 64;
    const __half* Kb = K + (size_t)(b * NKV  + kvh) * S_LEN * 64;
    const __half* Vb = V + (size_t)(b * NKV  + kvh) * S_LEN * 64;

    // stage Q
    for (int i = tid; i < 64 * 8; i += 128) {
        int r = i >> 3, c = (i & 7) * 8;
        *(uint4*)&Qs[r][c] = *(const uint4*)(Qb + (size_t)r * 64 + c);
    }

    // cp.async K/V loader: thread covers row tid>>1, 64B half-row (tid&1)
    int lr = tid >> 1;
    int lcb = (tid & 1) * 64;          // byte offset in 128B data row
    uint32_t ks_base[2], vs_base[2];
    ks_base[0] = (uint32_t)__cvta_generic_to_shared(&Ks[0][0][0]);
    ks_base[1] = (uint32_t)__cvta_generic_to_shared(&Ks[1][0][0]);
    vs_base[0] = (uint32_t)__cvta_generic_to_shared(&Vs[0][0][0]);
    vs_base[1] = (uint32_t)__cvta_generic_to_shared(&Vs[1][0][0]);

    int nkt = qt + 1;

    // prologue: load tile 0 into buffer 0
    {
        #pragma unroll
        for (int j = 0; j < 4; j++) {
            uint32_t so = (uint32_t)(lr * 144 + lcb + j * 16);
            cp16s(ks_base[0] + so, Kb + (size_t)lr * 64 + (lcb >> 1) + j * 8);
            cp16s(vs_base[0] + so, Vb + (size_t)lr * 64 + (lcb >> 1) + j * 8);
        }
        asm volatile("cp.async.commit_group;" ::: "memory");
    }

    __syncthreads();   // Q staged (also covered below, but fragments need it now)

    // hoist Q fragments (loop-invariant across kv tiles)
    int row_a = 16 * wid + g;
    unsigned qa[4][4];
    #pragma unroll
    for (int c4 = 0; c4 < 4; c4++) {
        int kk = c4 * 16;
        qa[c4][0] = *(const unsigned*)&Qs[row_a][kk + 2 * q];
        qa[c4][1] = *(const unsigned*)&Qs[row_a + 8][kk + 2 * q];
        qa[c4][2] = *(const unsigned*)&Qs[row_a][kk + 2 * q + 8];
        qa[c4][3] = *(const unsigned*)&Qs[row_a + 8][kk + 2 * q + 8];
    }

    float m0 = -INFINITY, m1 = -INFINITY, l0 = 0.f, l1 = 0.f;
    float o[8][4];
    #pragma unroll
    for (int nt = 0; nt < 8; nt++)
        #pragma unroll
        for (int r = 0; r < 4; r++) o[nt][r] = 0.f;

    int vmat = lane >> 3;          // 0..3
    int vrow = lane & 7;           // 0..7

    for (int jt = 0; jt < nkt; ++jt) {
        int buf = jt & 1;
        // prefetch next tile into the other buffer
        if (jt + 1 < nkt) {
            int nb = buf ^ 1;
            int j1 = (jt + 1) * 64;
            #pragma unroll
            for (int j = 0; j < 4; j++) {
                uint32_t so = (uint32_t)(lr * 144 + lcb + j * 16);
                cp16s(ks_base[nb] + so, Kb + (size_t)(j1 + lr) * 64 + (lcb >> 1) + j * 8);
                cp16s(vs_base[nb] + so, Vb + (size_t)(j1 + lr) * 64 + (lcb >> 1) + j * 8);
            }
            asm volatile("cp.async.commit_group;" ::: "memory");
            asm volatile("cp.async.wait_group 1;" ::: "memory");
        } else {
            asm volatile("cp.async.wait_group 0;" ::: "memory");
        }
        __syncthreads();

        // ---- S = Q K^T ----
        float s[8][4];
        #pragma unroll
        for (int nt = 0; nt < 8; nt++)
            #pragma unroll
            for (int r = 0; r < 4; r++) s[nt][r] = 0.f;

        #pragma unroll
        for (int c4 = 0; c4 < 4; c4++) {
            int kk = c4 * 16;
            #pragma unroll
            for (int nt = 0; nt < 8; nt++) {
                unsigned b0 = *(const unsigned*)&Ks[buf][nt * 8 + g][kk + 2 * q];
                unsigned b1 = *(const unsigned*)&Ks[buf][nt * 8 + g][kk + 2 * q + 8];
                asm volatile(
                    "mma.sync.aligned.m16n8k16.row.col.f32.f16.f16.f32 "
                    "{%0,%1,%2,%3}, {%4,%5,%6,%7}, {%8,%9}, {%0,%1,%2,%3};"
                    : "+f"(s[nt][0]), "+f"(s[nt][1]), "+f"(s[nt][2]), "+f"(s[nt][3])
                    : "r"(qa[c4][0]), "r"(qa[c4][1]), "r"(qa[c4][2]), "r"(qa[c4][3]),
                      "r"(b0), "r"(b1));
            }
        }

        // ---- causal mask (diagonal tile only) ----
        if (jt == qt) {
            #pragma unroll
            for (int nt = 0; nt < 8; nt++) {
                int col = nt * 8 + 2 * q;
                if (col     > row_a)     s[nt][0] = -INFINITY;
                if (col + 1 > row_a)     s[nt][1] = -INFINITY;
                if (col     > row_a + 8) s[nt][2] = -INFINITY;
                if (col + 1 > row_a + 8) s[nt][3] = -INFINITY;
            }
        }

        // ---- online softmax ----
        float mt0 = -INFINITY, mt1 = -INFINITY;
        #pragma unroll
        for (int nt = 0; nt < 8; nt++) {
            mt0 = fmaxf(mt0, fmaxf(s[nt][0], s[nt][1]));
            mt1 = fmaxf(mt1, fmaxf(s[nt][2], s[nt][3]));
        }
        #pragma unroll
        for (int off = 1; off < 4; off <<= 1) {
            mt0 = fmaxf(mt0, __shfl_xor_sync(0xffffffffu, mt0, off));
            mt1 = fmaxf(mt1, __shfl_xor_sync(0xffffffffu, mt1, off));
        }
        float mn0 = fmaxf(m0, mt0), mn1 = fmaxf(m1, mt1);
        float al0 = __expf(m0 - mn0), al1 = __expf(m1 - mn1);
        m0 = mn0; m1 = mn1;
        float ps0 = 0.f, ps1 = 0.f;
        #pragma unroll
        for (int nt = 0; nt < 8; nt++) {
            s[nt][0] = __expf(s[nt][0] - mn0);
            s[nt][1] = __expf(s[nt][1] - mn0);
            s[nt][2] = __expf(s[nt][2] - mn1);
            s[nt][3] = __expf(s[nt][3] - mn1);
            ps0 += s[nt][0] + s[nt][1];
            ps1 += s[nt][2] + s[nt][3];
            o[nt][0] *= al0; o[nt][1] *= al0;
            o[nt][2] *= al1; o[nt][3] *= al1;
        }
        #pragma unroll
        for (int off = 1; off < 4; off <<= 1) {
            ps0 += __shfl_xor_sync(0xffffffffu, ps0, off);
            ps1 += __shfl_xor_sync(0xffffffffu, ps1, off);
        }
        l0 = l0 * al0 + ps0;
        l1 = l1 * al1 + ps1;

        // ---- O += P V ----
        #pragma unroll
        for (int kc = 0; kc < 4; kc++) {
            unsigned a0 = packh2(s[2 * kc][0],     s[2 * kc][1]);
            unsigned a1 = packh2(s[2 * kc][2],     s[2 * kc][3]);
            unsigned a2 = packh2(s[2 * kc + 1][0], s[2 * kc + 1][1]);
            unsigned a3 = packh2(s[2 * kc + 1][2], s[2 * kc + 1][3]);
            #pragma unroll
            for (int ntp = 0; ntp < 4; ntp++) {
                const __half* vp = &Vs[buf][kc * 16 + (vmat & 1) * 8 + vrow]
                                          [ntp * 16 + (vmat >> 1) * 8];
                uint32_t vaddr = (uint32_t)__cvta_generic_to_shared(vp);
                unsigned v0, v1, v2, v3;
                asm volatile(
                    "ldmatrix.sync.aligned.m8n8.x4.trans.shared.b16 {%0,%1,%2,%3}, [%4];"
                    : "=r"(v0), "=r"(v1), "=r"(v2), "=r"(v3) : "r"(vaddr));
                asm volatile(
                    "mma.sync.aligned.m16n8k16.row.col.f32.f16.f16.f32 "
                    "{%0,%1,%2,%3}, {%4,%5,%6,%7}, {%8,%9}, {%0,%1,%2,%3};"
                    : "+f"(o[2 * ntp][0]), "+f"(o[2 * ntp][1]),
                      "+f"(o[2 * ntp][2]), "+f"(o[2 * ntp][3])
                    : "r"(a0), "r"(a1), "r"(a2), "r"(a3), "r"(v0), "r"(v1));
                asm volatile(
                    "mma.sync.aligned.m16n8k16.row.col.f32.f16.f16.f32 "
                    "{%0,%1,%2,%3}, {%4,%5,%6,%7}, {%8,%9}, {%0,%1,%2,%3};"
                    : "+f"(o[2 * ntp + 1][0]), "+f"(o[2 * ntp + 1][1]),
                      "+f"(o[2 * ntp + 1][2]), "+f"(o[2 * ntp + 1][3])
                    : "r"(a0), "r"(a1), "r"(a2), "r"(a3), "r"(v2), "r"(v3));
            }
        }
        __syncthreads();   // protect buf reuse by the prefetch two iterations out
    }

    // ---- epilogue ----
    float inv0 = 1.0f / l0, inv1 = 1.0f / l1;
    int srow0 = q0 + row_a;
    int srow1 = srow0 + 8;
    #pragma unroll
    for (int nt = 0; nt < 8; nt++) {
        int c = h * 64 + nt * 8 + 2 * q;
        *(unsigned*)(O + ((size_t)srow0 * BATCH + b) * DMODEL + c) =
            packh2(o[nt][0] * inv0, o[nt][1] * inv0);
        *(unsigned*)(O + ((size_t)srow1 * BATCH + b) * DMODEL + c) =
            packh2(o[nt][2] * inv1, o[nt][3] * inv1);
    }
}

// ---------------- host orchestration ----------------
extern "C" void kernel_launch(void* const* d_in, const int* in_sizes, int n_in,
                              void* d_out, int out_size)
{
    const float* x   = (const float*)d_in[0];
    const float* n1w = (const float*)d_in[1];
    const float* wq  = (const float*)d_in[2];
    const float* bq  = (const float*)d_in[3];
    const float* wk  = (const float*)d_in[4];
    const float* bk  = (const float*)d_in[5];
    const float* wv  = (const float*)d_in[6];
    const float* bv  = (const float*)d_in[7];
    const float* qnw = (const float*)d_in[8];
    const float* knw = (const float*)d_in[9];
    const float* wo  = (const float*)d_in[10];
    const float* bo  = (const float*)d_in[11];
    const float* n2w = (const float*)d_in[12];
    const float* w1  = (const float*)d_in[13];
    const float* b1  = (const float*)d_in[14];
    const float* w2  = (const float*)d_in[15];
    const float* b2  = (const float*)d_in[16];

    __half *ph, *pwqkv, *pqkv, *pattn, *ph2, *pmid, *pwor, *pw1r, *pw2r, *pq, *pk, *pv;
    float *pbqkv, *px1;
    cudaGetSymbolAddress((void**)&ph,    g_h);
    cudaGetSymbolAddress((void**)&pwqkv, g_wqkv);
    cudaGetSymbolAddress((void**)&pbqkv, g_bqkv);
    cudaGetSymbolAddress((void**)&pqkv,  g_qkv);
    cudaGetSymbolAddress((void**)&pq,    g_q);
    cudaGetSymbolAddress((void**)&pk,    g_k);
    cudaGetSymbolAddress((void**)&pv,    g_v);
    cudaGetSymbolAddress((void**)&pattn, g_attn);
    cudaGetSymbolAddress((void**)&px1,   g_x1);
    cudaGetSymbolAddress((void**)&ph2,   g_h2);
    cudaGetSymbolAddress((void**)&pmid,  g_mid);
    cudaGetSymbolAddress((void**)&pwor,  g_wor);
    cudaGetSymbolAddress((void**)&pw1r,  g_w1r);
    cudaGetSymbolAddress((void**)&pw2r,  g_w2r);

    cudaFuncSetAttribute(gemm_f16_kernel<1>,
                         cudaFuncAttributeMaxDynamicSharedMemorySize, GF_SMEM_BYTES);
    cudaFuncSetAttribute(gemm_f16_kernel<2>,
                         cudaFuncAttributeMaxDynamicSharedMemorySize, GF_SMEM_BYTES);
    cudaFuncSetAttribute(gemm_f16_kernel<3>,
                         cudaFuncAttributeMaxDynamicSharedMemorySize, GF_SMEM_BYTES);

    // weight prep (fp16 transposes to [N,K])
    pack_wqkv_t_kernel<<<dim3(QKVN / 32, DMODEL / 32), 256>>>(wq, wk, wv, pwqkv);
    packbias_kernel<<<6, 256>>>(bq, bk, bv, pbqkv);
    transpose_h_kernel<<<dim3(DMODEL / 32, DMODEL / 32), 256>>>(wo, pwor, DMODEL, DMODEL);
    transpose_h_kernel<<<dim3(DFF / 32, DMODEL / 32), 256>>>(w1, pw1r, DMODEL, DFF);
    transpose_h_kernel<<<dim3(DMODEL / 32, DFF / 32), 256>>>(w2, pw2r, DFF, DMODEL);

    rmsnorm_kernel<<<NTOK, 256>>>(x, n1w, ph);
    gemm_f16_kernel<3><<<dim3(QKVN / 128, NTOK / 128), 128, GF_SMEM_BYTES>>>(
        ph, pwqkv, pbqkv, nullptr, pqkv, NTOK, QKVN, DMODEL);
    qkrope_kernel<<<dim3(NTOK, 6), dim3(64, 4)>>>(pqkv, qnw, knw, pq, pk, pv);
    attn_f16_kernel<<<dim3(S_LEN / 64, BATCH * NHEAD), 128>>>(pq, pk, pv, pattn);
    gemm_f16_kernel<2><<<dim3(DMODEL / 128, NTOK / 128), 128, GF_SMEM_BYTES>>>(
        pattn, pwor, bo, x, px1, NTOK, DMODEL, DMODEL);
    rmsnorm_kernel<<<NTOK, 256>>>(px1, n2w, ph2);
    gemm_f16_kernel<1><<<dim3(DFF / 128, NTOK / 128), 128, GF_SMEM_BYTES>>>(
        ph2, pw1r, b1, nullptr, pmid, NTOK, DFF, DMODEL);
    gemm_f16_kernel<2><<<dim3(DMODEL / 128, NTOK / 128), 128, GF_SMEM_BYTES>>>(
        pmid, pw2r, b2, px1, d_out, NTOK, DMODEL, DFF);
}

// round 13
// speedup vs baseline: 1.0297x; 1.0297x over previous
#include <cuda_runtime.h>
#include <cuda_fp16.h>
#include <math.h>
#include <stdint.h>

#define S_LEN   2048
#define BATCH   2
#define DMODEL  1024
#define NHEAD   16
#define NKV     4
#define HEADDIM 64
#define NTOK    4096            // S_LEN * BATCH
#define DFF     4096            // 4 * DMODEL
#define QKVN    1536            // 1024 + 256 + 256
#define EPS_F   1e-5f
#define QK_SCALE 0.03125f       // D^-0.5 = 1/32

// fp16 GEMM smem: 4 stages, tiles [128 rows][40 halfs] (stride 80B)
#define GF_TILE_BYTES 10240     // 128*80
#define GF_STAGES 4
#define GF_SMEM_BYTES (2 * GF_STAGES * GF_TILE_BYTES)   // 81920

// ---------------- scratch (__device__ globals; no allocation allowed) ----------------
__device__ __half g_h   [NTOK * DMODEL];
__device__ __half g_wqkv[QKVN * DMODEL];      // transposed [N,K]
__device__ float  g_bqkv[QKVN];
__device__ __half g_qkv [NTOK * QKVN];
__device__ __half g_q   [BATCH * NHEAD * S_LEN * HEADDIM];
__device__ __half g_k   [BATCH * NKV   * S_LEN * HEADDIM];
__device__ __half g_v   [BATCH * NKV   * S_LEN * HEADDIM];
__device__ __half g_attn[NTOK * DMODEL];
__device__ float  g_x1  [NTOK * DMODEL];
__device__ __half g_h2  [NTOK * DMODEL];
__device__ __half g_mid [NTOK * DFF];
__device__ __half g_wor [DMODEL * DMODEL];    // transposed
__device__ __half g_w1r [DFF * DMODEL];       // transposed
__device__ __half g_w2r [DMODEL * DFF];       // transposed

__device__ __forceinline__ void cp16s(uint32_t daddr, const void* src) {
    asm volatile("cp.async.ca.shared.global [%0], [%1], 16;" :: "r"(daddr), "l"(src));
}
__device__ __forceinline__ unsigned packh2(float a, float b) {
    __half2 h = __floats2half2_rn(a, b);
    return *(unsigned*)&h;
}

// ---------------- pack wq|wk|wv transposed: Wt[c][k] fp16 ----------------
__global__ __launch_bounds__(256)
void pack_wqkv_t_kernel(const float* __restrict__ wq, const float* __restrict__ wk,
                        const float* __restrict__ wv, __half* __restrict__ Wt)
{
    __shared__ float t[32][33];
    int bx = blockIdx.x * 32;   // c base
    int by = blockIdx.y * 32;   // k base
    int tx = threadIdx.x & 31;
    int ty = threadIdx.x >> 5;
    #pragma unroll
    for (int j = 0; j < 4; j++) {
        int k = by + ty + 8 * j;
        int c = bx + tx;
        float v;
        if (c < 1024)       v = wq[(size_t)k * 1024 + c];
        else if (c < 1280)  v = wk[(size_t)k * 256 + (c - 1024)];
        else                v = wv[(size_t)k * 256 + (c - 1280)];
        t[ty + 8 * j][tx] = v;
    }
    __syncthreads();
    #pragma unroll
    for (int j = 0; j < 4; j++) {
        int c = bx + ty + 8 * j;
        Wt[(size_t)c * DMODEL + by + tx] = __float2half_rn(t[tx][ty + 8 * j]);
    }
}

// ---------------- fp16 transpose: dst[C][R] = half(src[R][C]) ----------------
__global__ __launch_bounds__(256)
void transpose_h_kernel(const float* __restrict__ src, __half* __restrict__ dst,
                        int R, int C)
{
    __shared__ float t[32][33];
    int bx = blockIdx.x * 32;   // C base
    int by = blockIdx.y * 32;   // R base
    int tx = threadIdx.x & 31;
    int ty = threadIdx.x >> 5;
    #pragma unroll
    for (int j = 0; j < 4; j++)
        t[ty + 8 * j][tx] = src[(size_t)(by + ty + 8 * j) * C + bx + tx];
    __syncthreads();
    #pragma unroll
    for (int j = 0; j < 4; j++)
        dst[(size_t)(bx + ty + 8 * j) * R + by + tx] = __float2half_rn(t[tx][ty + 8 * j]);
}

__global__ void packbias_kernel(const float* __restrict__ bq, const float* __restrict__ bk,
                                const float* __restrict__ bv, float* __restrict__ bias)
{
    int i = blockIdx.x * 256 + threadIdx.x;
    if (i < QKVN)
        bias[i] = (i < 1024) ? bq[i] : (i < 1280 ? bk[i - 1024] : bv[i - 1280]);
}

// ---------------- RMSNorm over D=1024, fp16 output ----------------
__global__ __launch_bounds__(256)
void rmsnorm_kernel(const float* __restrict__ x, const float* __restrict__ w,
                    __half* __restrict__ y)
{
    int row = blockIdx.x;
    int i = threadIdx.x;
    const float* xr = x + (size_t)row * DMODEL;
    float4 xv = *(const float4*)(xr + i * 4);
    float ss = xv.x * xv.x + xv.y * xv.y + xv.z * xv.z + xv.w * xv.w;
    #pragma unroll
    for (int off = 16; off; off >>= 1) ss += __shfl_xor_sync(0xffffffffu, ss, off);
    __shared__ float red[8];
    __shared__ float s_sc;
    if ((i & 31) == 0) red[i >> 5] = ss;
    __syncthreads();
    if (i == 0) {
        float tot = 0.f;
        #pragma unroll
        for (int kk = 0; kk < 8; kk++) tot += red[kk];
        s_sc = rsqrtf(tot * (1.0f / DMODEL) + EPS_F);
    }
    __syncthreads();
    float sc = s_sc;
    float4 wv = *(const float4*)(w + i * 4);
    uint2 u;
    u.x = packh2(xv.x * sc * wv.x, xv.y * sc * wv.y);
    u.y = packh2(xv.z * sc * wv.z, xv.w * sc * wv.w);
    *(uint2*)(y + (size_t)row * DMODEL + i * 4) = u;
}

// ---------------- per-head QK RMSNorm + RoPE + relayout (fp16 in/out) ----------------
__global__ __launch_bounds__(256)
void qkrope_kernel(const __half* __restrict__ qkv, const float* __restrict__ qn_w,
                   const float* __restrict__ kn_w, __half* __restrict__ Qo,
                   __half* __restrict__ Ko, __half* __restrict__ Vo)
{
    int t = blockIdx.x;            // token = s*BATCH + b
    int ty = threadIdx.y;          // 0..3
    int slot = blockIdx.y * 4 + ty;
    int i = threadIdx.x;           // 0..63
    int s = t / BATCH, b = t % BATCH;
    __shared__ float buf[4][64];
    __shared__ float red[4][2];

    if (slot >= 20) {   // V: pure relayout (whole block is V)
        int vh = slot - 20;
        Vo[((size_t)(b * NKV + vh) * S_LEN + s) * 64 + i] =
            qkv[(size_t)t * QKVN + 1280 + vh * 64 + i];
        return;
    }

    bool is_q = (slot < 16);
    int col = is_q ? (slot * 64 + i) : (1024 + (slot - 16) * 64 + i);
    float v = __half2float(qkv[(size_t)t * QKVN + col]);
    float ss = v * v;
    #pragma unroll
    for (int off = 16; off; off >>= 1) ss += __shfl_xor_sync(0xffffffffu, ss, off);
    if ((i & 31) == 0) red[ty][i >> 5] = ss;
    __syncthreads();
    float tot = red[ty][0] + red[ty][1];
    float sc = rsqrtf(tot * (1.0f / 64.0f) + EPS_F);
    const float* w = is_q ? qn_w : kn_w;
    float nv = v * sc * w[i];
    buf[ty][i] = nv;
    __syncthreads();
    float rot = (i < 32) ? -buf[ty][i + 32] : buf[ty][i - 32];
    int j = i & 31;
    float invf = exp2f(-(float)j * (13.287712379549449f / 32.0f));
    float ang = (float)s * invf;
    float sn, cs;
    sincosf(ang, &sn, &cs);
    float outv = nv * cs + rot * sn;
    if (is_q) {
        outv *= QK_SCALE;
        Qo[((size_t)(b * NHEAD + slot) * S_LEN + s) * 64 + i] = __float2half_rn(outv);
    } else {
        Ko[((size_t)(b * NKV + (slot - 16)) * S_LEN + s) * 64 + i] = __float2half_rn(outv);
    }
}

// ---------------- fp16 GEMM stage loader: 8 cp.async per thread ----------------
__device__ __forceinline__ void gf_load(uint32_t sA, uint32_t sB,
                                        const __half* Ag, const __half* Bg,
                                        int K, int k0, int tid)
{
    int r0 = tid >> 2;             // 0..31
    int ch = (tid & 3) << 3;       // half offset in row: 0,8,16,24
    #pragma unroll
    for (int j = 0; j < 4; j++) {
        int r = r0 + 32 * j;
        uint32_t so = (uint32_t)(r * 80 + ch * 2);
        cp16s(sA + so, Ag + (size_t)r * K + k0 + ch);
        cp16s(sB + so, Bg + (size_t)r * K + k0 + ch);
    }
    asm volatile("cp.async.commit_group;" ::: "memory");
}

// ---------------- fp16 GEMM ----------------
// EPI: 0 = +bias fp32 out, 1 = gelu(+bias) fp16 out, 2 = +bias+residual fp32 out,
//      3 = +bias fp16 out
template<int EPI>
__global__ __launch_bounds__(128)
void gemm_f16_kernel(const __half* __restrict__ A, const __half* __restrict__ Bt,
                     const float* __restrict__ bias, const float* __restrict__ res,
                     void* __restrict__ Cout, int M, int N, int K)
{
    extern __shared__ char smc[];
    uint32_t smem_base;
    asm("{ .reg .u64 t; cvta.to.shared.u64 t, %1; cvt.u32.u64 %0, t; }"
        : "=r"(smem_base) : "l"(smc));

    int tid  = threadIdx.x;
    int wid  = tid >> 5, lane = tid & 31;
    int g    = lane >> 2;
    int q    = lane & 3;
    int wm   = (wid >> 1) * 64;
    int wn   = (wid & 1) * 64;

    int row0 = blockIdx.y * 128;
    int col0 = blockIdx.x * 128;
    const __half* Ag = A  + (size_t)row0 * K;
    const __half* Bg = Bt + (size_t)col0 * K;

    float acc[4][8][4];
    #pragma unroll
    for (int mt = 0; mt < 4; mt++)
        #pragma unroll
        for (int nt = 0; nt < 8; nt++)
            #pragma unroll
            for (int r = 0; r < 4; r++) acc[mt][nt][r] = 0.f;

    const int KT = K >> 5;

    #pragma unroll
    for (int st = 0; st < 3; st++)
        gf_load(smem_base + st * GF_TILE_BYTES,
                smem_base + (GF_STAGES + st) * GF_TILE_BYTES,
                Ag, Bg, K, st * 32, tid);

    for (int kt = 0; kt < KT; kt++) {
        asm volatile("cp.async.wait_group 2;" ::: "memory");
        __syncthreads();

        if (kt + 3 < KT) {
            int st = (kt + 3) & 3;
            gf_load(smem_base + st * GF_TILE_BYTES,
                    smem_base + (GF_STAGES + st) * GF_TILE_BYTES,
                    Ag, Bg, K, (kt + 3) * 32, tid);
        }

        int st = kt & 3;
        const __half* As = (const __half*)(smc + st * GF_TILE_BYTES);
        const __half* Bs = (const __half*)(smc + (GF_STAGES + st) * GF_TILE_BYTES);

        #pragma unroll
        for (int kk = 0; kk < 32; kk += 16) {
            unsigned af[4][4];
            #pragma unroll
            for (int mt = 0; mt < 4; mt++) {
                int r = wm + mt * 16 + g;
                af[mt][0] = *(const unsigned*)(As + r * 40 + kk + 2 * q);
                af[mt][1] = *(const unsigned*)(As + (r + 8) * 40 + kk + 2 * q);
                af[mt][2] = *(const unsigned*)(As + r * 40 + kk + 2 * q + 8);
                af[mt][3] = *(const unsigned*)(As + (r + 8) * 40 + kk + 2 * q + 8);
            }
            unsigned bf[8][2];
            #pragma unroll
            for (int nt = 0; nt < 8; nt++) {
                int c = wn + nt * 8 + g;
                bf[nt][0] = *(const unsigned*)(Bs + c * 40 + kk + 2 * q);
                bf[nt][1] = *(const unsigned*)(Bs + c * 40 + kk + 2 * q + 8);
            }
            #pragma unroll
            for (int mt = 0; mt < 4; mt++)
                #pragma unroll
                for (int nt = 0; nt < 8; nt++) {
                    asm volatile(
                        "mma.sync.aligned.m16n8k16.row.col.f32.f16.f16.f32 "
                        "{%0,%1,%2,%3}, {%4,%5,%6,%7}, {%8,%9}, {%0,%1,%2,%3};"
                        : "+f"(acc[mt][nt][0]), "+f"(acc[mt][nt][1]),
                          "+f"(acc[mt][nt][2]), "+f"(acc[mt][nt][3])
                        : "r"(af[mt][0]), "r"(af[mt][1]), "r"(af[mt][2]), "r"(af[mt][3]),
                          "r"(bf[nt][0]), "r"(bf[nt][1]));
                }
        }
    }

    #pragma unroll
    for (int mt = 0; mt < 4; mt++) {
        int r = row0 + wm + mt * 16 + g;
        #pragma unroll
        for (int nt = 0; nt < 8; nt++) {
            int c = col0 + wn + nt * 8 + 2 * q;
            float bv0 = bias[c], bv1 = bias[c + 1];
            float v00 = acc[mt][nt][0] + bv0;
            float v01 = acc[mt][nt][1] + bv1;
            float v10 = acc[mt][nt][2] + bv0;
            float v11 = acc[mt][nt][3] + bv1;
            if (EPI == 1) {
                v00 = 0.5f * v00 * (1.0f + erff(v00 * 0.70710678118654752f));
                v01 = 0.5f * v01 * (1.0f + erff(v01 * 0.70710678118654752f));
                v10 = 0.5f * v10 * (1.0f + erff(v10 * 0.70710678118654752f));
                v11 = 0.5f * v11 * (1.0f + erff(v11 * 0.70710678118654752f));
            }
            if (EPI == 1 || EPI == 3) {
                __half* C = (__half*)Cout;
                *(unsigned*)(C + (size_t)r * N + c)       = packh2(v00, v01);
                *(unsigned*)(C + (size_t)(r + 8) * N + c) = packh2(v10, v11);
            } else {
                float* C = (float*)Cout;
                if (EPI == 2) {
                    float2 r0 = *(const float2*)(res + (size_t)r * N + c);
                    float2 r1 = *(const float2*)(res + (size_t)(r + 8) * N + c);
                    v00 += r0.x; v01 += r0.y;
                    v10 += r1.x; v11 += r1.y;
                }
                *(float2*)(C + (size_t)r * N + c)       = make_float2(v00, v01);
                *(float2*)(C + (size_t)(r + 8) * N + c) = make_float2(v10, v11);
            }
        }
    }
}

// ---------------- fp16 flash attention (single-buffer, hoisted Q frags) ----------------
// BQ=64, BKV=64, 4 warps (warp w owns q-rows 16w..16w+15), causal, GQA.
__global__ __launch_bounds__(128)
void attn_f16_kernel(const __half* __restrict__ Q, const __half* __restrict__ K,
                     const __half* __restrict__ V, __half* __restrict__ O)
{
    __shared__ __half Qs[64][72];
    __shared__ __half Ks[64][72];
    __shared__ __half Vs[64][72];

    int tid  = threadIdx.x;
    int wid  = tid >> 5, lane = tid & 31;
    int g    = lane >> 2;
    int q    = lane & 3;
    int qt   = blockIdx.x;
    int bh   = blockIdx.y;
    int b    = bh >> 4;
    int h    = bh & 15;
    int kvh  = h >> 2;
    int q0   = qt * 64;

    const __half* Qb = Q + (size_t)(b * NHEAD + h)  * S_LEN * 64 + (size_t)q0 * 64;
    const __half* Kb = K + (size_t)(b * NKV  + kvh) * S_LEN * 64;
    const __half* Vb = V + (size_t)(b * NKV  + kvh) * S_LEN * 64;

    // stage Q: 64 rows x 64 halves (8x uint4 per row)
    for (int i = tid; i < 64 * 8; i += 128) {
        int r = i >> 3, c = (i & 7) * 8;
        *(uint4*)&Qs[r][c] = *(const uint4*)(Qb + (size_t)r * 64 + c);
    }
    __syncthreads();

    // hoist Q fragments (loop-invariant across kv tiles)
    int row_a = 16 * wid + g;
    unsigned qa[4][4];
    #pragma unroll
    for (int c4 = 0; c4 < 4; c4++) {
        int kk = c4 * 16;
        qa[c4][0] = *(const unsigned*)&Qs[row_a][kk + 2 * q];
        qa[c4][1] = *(const unsigned*)&Qs[row_a + 8][kk + 2 * q];
        qa[c4][2] = *(const unsigned*)&Qs[row_a][kk + 2 * q + 8];
        qa[c4][3] = *(const unsigned*)&Qs[row_a + 8][kk + 2 * q + 8];
    }

    float m0 = -INFINITY, m1 = -INFINITY, l0 = 0.f, l1 = 0.f;
    float o[8][4];
    #pragma unroll
    for (int nt = 0; nt < 8; nt++)
        #pragma unroll
        for (int r = 0; r < 4; r++) o[nt][r] = 0.f;

    int nkt = qt + 1;
    int vmat = lane >> 3;          // 0..3
    int vrow = lane & 7;           // 0..7

    for (int jt = 0; jt < nkt; ++jt) {
        int j0 = jt * 64;
        __syncthreads();
        for (int i = tid; i < 64 * 8; i += 128) {
            int r = i >> 3, c = (i & 7) * 8;
            *(uint4*)&Ks[r][c] = *(const uint4*)(Kb + (size_t)(j0 + r) * 64 + c);
            *(uint4*)&Vs[r][c] = *(const uint4*)(Vb + (size_t)(j0 + r) * 64 + c);
        }
        __syncthreads();

        // ---- S = Q K^T ----
        float s[8][4];
        #pragma unroll
        for (int nt = 0; nt < 8; nt++)
            #pragma unroll
            for (int r = 0; r < 4; r++) s[nt][r] = 0.f;

        #pragma unroll
        for (int c4 = 0; c4 < 4; c4++) {
            int kk = c4 * 16;
            #pragma unroll
            for (int nt = 0; nt < 8; nt++) {
                unsigned b0 = *(const unsigned*)&Ks[nt * 8 + g][kk + 2 * q];
                unsigned b1 = *(const unsigned*)&Ks[nt * 8 + g][kk + 2 * q + 8];
                asm volatile(
                    "mma.sync.aligned.m16n8k16.row.col.f32.f16.f16.f32 "
                    "{%0,%1,%2,%3}, {%4,%5,%6,%7}, {%8,%9}, {%0,%1,%2,%3};"
                    : "+f"(s[nt][0]), "+f"(s[nt][1]), "+f"(s[nt][2]), "+f"(s[nt][3])
                    : "r"(qa[c4][0]), "r"(qa[c4][1]), "r"(qa[c4][2]), "r"(qa[c4][3]),
                      "r"(b0), "r"(b1));
            }
        }

        // ---- causal mask (diagonal tile only) ----
        if (jt == qt) {
            #pragma unroll
            for (int nt = 0; nt < 8; nt++) {
                int col = nt * 8 + 2 * q;
                if (col     > row_a)     s[nt][0] = -INFINITY;
                if (col + 1 > row_a)     s[nt][1] = -INFINITY;
                if (col     > row_a + 8) s[nt][2] = -INFINITY;
                if (col + 1 > row_a + 8) s[nt][3] = -INFINITY;
            }
        }

        // ---- online softmax ----
        float mt0 = -INFINITY, mt1 = -INFINITY;
        #pragma unroll
        for (int nt = 0; nt < 8; nt++) {
            mt0 = fmaxf(mt0, fmaxf(s[nt][0], s[nt][1]));
            mt1 = fmaxf(mt1, fmaxf(s[nt][2], s[nt][3]));
        }
        #pragma unroll
        for (int off = 1; off < 4; off <<= 1) {
            mt0 = fmaxf(mt0, __shfl_xor_sync(0xffffffffu, mt0, off));
            mt1 = fmaxf(mt1, __shfl_xor_sync(0xffffffffu, mt1, off));
        }
        float mn0 = fmaxf(m0, mt0), mn1 = fmaxf(m1, mt1);
        float al0 = __expf(m0 - mn0), al1 = __expf(m1 - mn1);
        m0 = mn0; m1 = mn1;
        float ps0 = 0.f, ps1 = 0.f;
        #pragma unroll
        for (int nt = 0; nt < 8; nt++) {
            s[nt][0] = __expf(s[nt][0] - mn0);
            s[nt][1] = __expf(s[nt][1] - mn0);
            s[nt][2] = __expf(s[nt][2] - mn1);
            s[nt][3] = __expf(s[nt][3] - mn1);
            ps0 += s[nt][0] + s[nt][1];
            ps1 += s[nt][2] + s[nt][3];
            o[nt][0] *= al0; o[nt][1] *= al0;
            o[nt][2] *= al1; o[nt][3] *= al1;
        }
        #pragma unroll
        for (int off = 1; off < 4; off <<= 1) {
            ps0 += __shfl_xor_sync(0xffffffffu, ps0, off);
            ps1 += __shfl_xor_sync(0xffffffffu, ps1, off);
        }
        l0 = l0 * al0 + ps0;
        l1 = l1 * al1 + ps1;

        // ---- O += P V : C-frag of S -> A-frag directly; V via ldmatrix.trans ----
        #pragma unroll
        for (int kc = 0; kc < 4; kc++) {
            unsigned a0 = packh2(s[2 * kc][0],     s[2 * kc][1]);
            unsigned a1 = packh2(s[2 * kc][2],     s[2 * kc][3]);
            unsigned a2 = packh2(s[2 * kc + 1][0], s[2 * kc + 1][1]);
            unsigned a3 = packh2(s[2 * kc + 1][2], s[2 * kc + 1][3]);
            #pragma unroll
            for (int ntp = 0; ntp < 4; ntp++) {
                const __half* vp = &Vs[kc * 16 + (vmat & 1) * 8 + vrow]
                                      [ntp * 16 + (vmat >> 1) * 8];
                uint32_t vaddr = (uint32_t)__cvta_generic_to_shared(vp);
                unsigned v0, v1, v2, v3;
                asm volatile(
                    "ldmatrix.sync.aligned.m8n8.x4.trans.shared.b16 {%0,%1,%2,%3}, [%4];"
                    : "=r"(v0), "=r"(v1), "=r"(v2), "=r"(v3) : "r"(vaddr));
                asm volatile(
                    "mma.sync.aligned.m16n8k16.row.col.f32.f16.f16.f32 "
                    "{%0,%1,%2,%3}, {%4,%5,%6,%7}, {%8,%9}, {%0,%1,%2,%3};"
                    : "+f"(o[2 * ntp][0]), "+f"(o[2 * ntp][1]),
                      "+f"(o[2 * ntp][2]), "+f"(o[2 * ntp][3])
                    : "r"(a0), "r"(a1), "r"(a2), "r"(a3), "r"(v0), "r"(v1));
                asm volatile(
                    "mma.sync.aligned.m16n8k16.row.col.f32.f16.f16.f32 "
                    "{%0,%1,%2,%3}, {%4,%5,%6,%7}, {%8,%9}, {%0,%1,%2,%3};"
                    : "+f"(o[2 * ntp + 1][0]), "+f"(o[2 * ntp + 1][1]),
                      "+f"(o[2 * ntp + 1][2]), "+f"(o[2 * ntp + 1][3])
                    : "r"(a0), "r"(a1), "r"(a2), "r"(a3), "r"(v2), "r"(v3));
            }
        }
    }

    // ---- epilogue: normalize, write fp16 [token, D] ----
    float inv0 = 1.0f / l0, inv1 = 1.0f / l1;
    int srow0 = q0 + row_a;
    int srow1 = srow0 + 8;
    #pragma unroll
    for (int nt = 0; nt < 8; nt++) {
        int c = h * 64 + nt * 8 + 2 * q;
        *(unsigned*)(O + ((size_t)srow0 * BATCH + b) * DMODEL + c) =
            packh2(o[nt][0] * inv0, o[nt][1] * inv0);
        *(unsigned*)(O + ((size_t)srow1 * BATCH + b) * DMODEL + c) =
            packh2(o[nt][2] * inv1, o[nt][3] * inv1);
    }
}

// ---------------- host orchestration ----------------
extern "C" void kernel_launch(void* const* d_in, const int* in_sizes, int n_in,
                              void* d_out, int out_size)
{
    const float* x   = (const float*)d_in[0];
    const float* n1w = (const float*)d_in[1];
    const float* wq  = (const float*)d_in[2];
    const float* bq  = (const float*)d_in[3];
    const float* wk  = (const float*)d_in[4];
    const float* bk  = (const float*)d_in[5];
    const float* wv  = (const float*)d_in[6];
    const float* bv  = (const float*)d_in[7];
    const float* qnw = (const float*)d_in[8];
    const float* knw = (const float*)d_in[9];
    const float* wo  = (const float*)d_in[10];
    const float* bo  = (const float*)d_in[11];
    const float* n2w = (const float*)d_in[12];
    const float* w1  = (const float*)d_in[13];
    const float* b1  = (const float*)d_in[14];
    const float* w2  = (const float*)d_in[15];
    const float* b2  = (const float*)d_in[16];

    __half *ph, *pwqkv, *pqkv, *pattn, *ph2, *pmid, *pwor, *pw1r, *pw2r, *pq, *pk, *pv;
    float *pbqkv, *px1;
    cudaGetSymbolAddress((void**)&ph,    g_h);
    cudaGetSymbolAddress((void**)&pwqkv, g_wqkv);
    cudaGetSymbolAddress((void**)&pbqkv, g_bqkv);
    cudaGetSymbolAddress((void**)&pqkv,  g_qkv);
    cudaGetSymbolAddress((void**)&pq,    g_q);
    cudaGetSymbolAddress((void**)&pk,    g_k);
    cudaGetSymbolAddress((void**)&pv,    g_v);
    cudaGetSymbolAddress((void**)&pattn, g_attn);
    cudaGetSymbolAddress((void**)&px1,   g_x1);
    cudaGetSymbolAddress((void**)&ph2,   g_h2);
    cudaGetSymbolAddress((void**)&pmid,  g_mid);
    cudaGetSymbolAddress((void**)&pwor,  g_wor);
    cudaGetSymbolAddress((void**)&pw1r,  g_w1r);
    cudaGetSymbolAddress((void**)&pw2r,  g_w2r);

    cudaFuncSetAttribute(gemm_f16_kernel<1>,
                         cudaFuncAttributeMaxDynamicSharedMemorySize, GF_SMEM_BYTES);
    cudaFuncSetAttribute(gemm_f16_kernel<2>,
                         cudaFuncAttributeMaxDynamicSharedMemorySize, GF_SMEM_BYTES);
    cudaFuncSetAttribute(gemm_f16_kernel<3>,
                         cudaFuncAttributeMaxDynamicSharedMemorySize, GF_SMEM_BYTES);

    // weight prep (fp16 transposes to [N,K])
    pack_wqkv_t_kernel<<<dim3(QKVN / 32, DMODEL / 32), 256>>>(wq, wk, wv, pwqkv);
    packbias_kernel<<<6, 256>>>(bq, bk, bv, pbqkv);
    transpose_h_kernel<<<dim3(DMODEL / 32, DMODEL / 32), 256>>>(wo, pwor, DMODEL, DMODEL);
    transpose_h_kernel<<<dim3(DFF / 32, DMODEL / 32), 256>>>(w1, pw1r, DMODEL, DFF);
    transpose_h_kernel<<<dim3(DMODEL / 32, DFF / 32), 256>>>(w2, pw2r, DFF, DMODEL);

    rmsnorm_kernel<<<NTOK, 256>>>(x, n1w, ph);
    gemm_f16_kernel<3><<<dim3(QKVN / 128, NTOK / 128), 128, GF_SMEM_BYTES>>>(
        ph, pwqkv, pbqkv, nullptr, pqkv, NTOK, QKVN, DMODEL);
    qkrope_kernel<<<dim3(NTOK, 6), dim3(64, 4)>>>(pqkv, qnw, knw, pq, pk, pv);
    attn_f16_kernel<<<dim3(S_LEN / 64, BATCH * NHEAD), 128>>>(pq, pk, pv, pattn);
    gemm_f16_kernel<2><<<dim3(DMODEL / 128, NTOK / 128), 128, GF_SMEM_BYTES>>>(
        pattn, pwor, bo, x, px1, NTOK, DMODEL, DMODEL);
    rmsnorm_kernel<<<NTOK, 256>>>(px1, n2w, ph2);
    gemm_f16_kernel<1><<<dim3(DFF / 128, NTOK / 128), 128, GF_SMEM_BYTES>>>(
        ph2, pw1r, b1, nullptr, pmid, NTOK, DFF, DMODEL);
    gemm_f16_kernel<2><<<dim3(DMODEL / 128, NTOK / 128), 128, GF_SMEM_BYTES>>>(
        pmid, pw2r, b2, px1, d_out, NTOK, DMODEL, DFF);
}

// round 14
// speedup vs baseline: 1.0376x; 1.0077x over previous
#include <cuda_runtime.h>
#include <cuda_fp16.h>
#include <math.h>
#include <stdint.h>

#define S_LEN   2048
#define BATCH   2
#define DMODEL  1024
#define NHEAD   16
#define NKV     4
#define HEADDIM 64
#define NTOK    4096            // S_LEN * BATCH
#define DFF     4096            // 4 * DMODEL
#define QKVN    1536            // 1024 + 256 + 256
#define EPS_F   1e-5f
#define QK_SCALE 0.03125f       // D^-0.5 = 1/32

// fp16 GEMM smem: 4 stages, tiles [128 rows][40 halfs] (stride 80B)
#define GF_TILE_BYTES 10240     // 128*80
#define GF_STAGES 4
#define GF_SMEM_BYTES (2 * GF_STAGES * GF_TILE_BYTES)   // 81920

// fused prep grid ranges (32x32 tiles)
#define PREP_QKV_BLKS   (48 * 32)          // 1536
#define PREP_WO_BLKS    (32 * 32)          // 1024
#define PREP_W1_BLKS    (128 * 32)         // 4096
#define PREP_W2_BLKS    (32 * 128)         // 4096
#define PREP_TOTAL (PREP_QKV_BLKS + PREP_WO_BLKS + PREP_W1_BLKS + PREP_W2_BLKS)

// ---------------- scratch (__device__ globals; no allocation allowed) ----------------
__device__ __half g_h   [NTOK * DMODEL];
__device__ __half g_wqkv[QKVN * DMODEL];      // transposed [N,K]
__device__ float  g_bqkv[QKVN];
__device__ __half g_qkv [NTOK * QKVN];
__device__ __half g_q   [BATCH * NHEAD * S_LEN * HEADDIM];
__device__ __half g_k   [BATCH * NKV   * S_LEN * HEADDIM];
__device__ __half g_v   [BATCH * NKV   * S_LEN * HEADDIM];
__device__ __half g_attn[NTOK * DMODEL];
__device__ float  g_x1  [NTOK * DMODEL];
__device__ __half g_h2  [NTOK * DMODEL];
__device__ __half g_mid [NTOK * DFF];
__device__ __half g_wor [DMODEL * DMODEL];    // transposed
__device__ __half g_w1r [DFF * DMODEL];       // transposed
__device__ __half g_w2r [DMODEL * DFF];       // transposed

__device__ __forceinline__ void cp16s(uint32_t daddr, const void* src) {
    asm volatile("cp.async.ca.shared.global [%0], [%1], 16;" :: "r"(daddr), "l"(src));
}
__device__ __forceinline__ unsigned packh2(float a, float b) {
    __half2 h = __floats2half2_rn(a, b);
    return *(unsigned*)&h;
}

// ---------------- fused weight prep: all transposes + bias pack in one launch --------
// 32x32 fp32->fp16 transpose tile helper
__device__ __forceinline__ void tile_transpose(const float* __restrict__ src,
                                               __half* __restrict__ dst,
                                               int R, int C, int bx, int by, int tx, int ty)
{
    __shared__ float t[32][33];
    #pragma unroll
    for (int j = 0; j < 4; j++)
        t[ty + 8 * j][tx] = src[(size_t)(by + ty + 8 * j) * C + bx + tx];
    __syncthreads();
    #pragma unroll
    for (int j = 0; j < 4; j++)
        dst[(size_t)(bx + ty + 8 * j) * R + by + tx] = __float2half_rn(t[tx][ty + 8 * j]);
}

__global__ __launch_bounds__(256)
void prep_kernel(const float* __restrict__ wq, const float* __restrict__ wk,
                 const float* __restrict__ wv, const float* __restrict__ bq,
                 const float* __restrict__ bk, const float* __restrict__ bv,
                 const float* __restrict__ wo, const float* __restrict__ w1,
                 const float* __restrict__ w2,
                 __half* __restrict__ Wqkv, float* __restrict__ bias,
                 __half* __restrict__ Wor, __half* __restrict__ W1r,
                 __half* __restrict__ W2r)
{
    int blk = blockIdx.x;
    int tx = threadIdx.x & 31;
    int ty = threadIdx.x >> 5;

    if (blk < PREP_QKV_BLKS) {
        // pack wq|wk|wv transposed: Wqkv[c][k]
        __shared__ float t[32][33];
        int bx = (blk % 48) * 32;   // c base
        int by = (blk / 48) * 32;   // k base
        #pragma unroll
        for (int j = 0; j < 4; j++) {
            int k = by + ty + 8 * j;
            int c = bx + tx;
            float v;
            if (c < 1024)       v = wq[(size_t)k * 1024 + c];
            else if (c < 1280)  v = wk[(size_t)k * 256 + (c - 1024)];
            else                v = wv[(size_t)k * 256 + (c - 1280)];
            t[ty + 8 * j][tx] = v;
        }
        __syncthreads();
        #pragma unroll
        for (int j = 0; j < 4; j++) {
            int c = bx + ty + 8 * j;
            Wqkv[(size_t)c * DMODEL + by + tx] = __float2half_rn(t[tx][ty + 8 * j]);
        }
        // bias pack piggybacks on the first 6 blocks
        if (blk < 6) {
            int i = blk * 256 + threadIdx.x;
            if (i < QKVN)
                bias[i] = (i < 1024) ? bq[i] : (i < 1280 ? bk[i - 1024] : bv[i - 1280]);
        }
        return;
    }
    blk -= PREP_QKV_BLKS;
    if (blk < PREP_WO_BLKS) {
        tile_transpose(wo, Wor, DMODEL, DMODEL, (blk % 32) * 32, (blk / 32) * 32, tx, ty);
        return;
    }
    blk -= PREP_WO_BLKS;
    if (blk < PREP_W1_BLKS) {
        tile_transpose(w1, W1r, DMODEL, DFF, (blk % 128) * 32, (blk / 128) * 32, tx, ty);
        return;
    }
    blk -= PREP_W1_BLKS;
    tile_transpose(w2, W2r, DFF, DMODEL, (blk % 32) * 32, (blk / 32) * 32, tx, ty);
}

// ---------------- RMSNorm over D=1024, fp16 output ----------------
__global__ __launch_bounds__(256)
void rmsnorm_kernel(const float* __restrict__ x, const float* __restrict__ w,
                    __half* __restrict__ y)
{
    int row = blockIdx.x;
    int i = threadIdx.x;
    const float* xr = x + (size_t)row * DMODEL;
    float4 xv = *(const float4*)(xr + i * 4);
    float ss = xv.x * xv.x + xv.y * xv.y + xv.z * xv.z + xv.w * xv.w;
    #pragma unroll
    for (int off = 16; off; off >>= 1) ss += __shfl_xor_sync(0xffffffffu, ss, off);
    __shared__ float red[8];
    __shared__ float s_sc;
    if ((i & 31) == 0) red[i >> 5] = ss;
    __syncthreads();
    if (i == 0) {
        float tot = 0.f;
        #pragma unroll
        for (int kk = 0; kk < 8; kk++) tot += red[kk];
        s_sc = rsqrtf(tot * (1.0f / DMODEL) + EPS_F);
    }
    __syncthreads();
    float sc = s_sc;
    float4 wv = *(const float4*)(w + i * 4);
    uint2 u;
    u.x = packh2(xv.x * sc * wv.x, xv.y * sc * wv.y);
    u.y = packh2(xv.z * sc * wv.z, xv.w * sc * wv.w);
    *(uint2*)(y + (size_t)row * DMODEL + i * 4) = u;
}

// ---------------- per-head QK RMSNorm + RoPE + relayout (fp16 in/out) ----------------
__global__ __launch_bounds__(256)
void qkrope_kernel(const __half* __restrict__ qkv, const float* __restrict__ qn_w,
                   const float* __restrict__ kn_w, __half* __restrict__ Qo,
                   __half* __restrict__ Ko, __half* __restrict__ Vo)
{
    int t = blockIdx.x;            // token = s*BATCH + b
    int ty = threadIdx.y;          // 0..3
    int slot = blockIdx.y * 4 + ty;
    int i = threadIdx.x;           // 0..63
    int s = t / BATCH, b = t % BATCH;
    __shared__ float buf[4][64];
    __shared__ float red[4][2];

    if (slot >= 20) {   // V: pure relayout (whole block is V)
        int vh = slot - 20;
        Vo[((size_t)(b * NKV + vh) * S_LEN + s) * 64 + i] =
            qkv[(size_t)t * QKVN + 1280 + vh * 64 + i];
        return;
    }

    bool is_q = (slot < 16);
    int col = is_q ? (slot * 64 + i) : (1024 + (slot - 16) * 64 + i);
    float v = __half2float(qkv[(size_t)t * QKVN + col]);
    float ss = v * v;
    #pragma unroll
    for (int off = 16; off; off >>= 1) ss += __shfl_xor_sync(0xffffffffu, ss, off);
    if ((i & 31) == 0) red[ty][i >> 5] = ss;
    __syncthreads();
    float tot = red[ty][0] + red[ty][1];
    float sc = rsqrtf(tot * (1.0f / 64.0f) + EPS_F);
    const float* w = is_q ? qn_w : kn_w;
    float nv = v * sc * w[i];
    buf[ty][i] = nv;
    __syncthreads();
    float rot = (i < 32) ? -buf[ty][i + 32] : buf[ty][i - 32];
    int j = i & 31;
    float invf = exp2f(-(float)j * (13.287712379549449f / 32.0f));
    float ang = (float)s * invf;
    float sn, cs;
    sincosf(ang, &sn, &cs);
    float outv = nv * cs + rot * sn;
    if (is_q) {
        outv *= QK_SCALE;
        Qo[((size_t)(b * NHEAD + slot) * S_LEN + s) * 64 + i] = __float2half_rn(outv);
    } else {
        Ko[((size_t)(b * NKV + (slot - 16)) * S_LEN + s) * 64 + i] = __float2half_rn(outv);
    }
}

// ---------------- fp16 GEMM stage loader: 8 cp.async per thread ----------------
__device__ __forceinline__ void gf_load(uint32_t sA, uint32_t sB,
                                        const __half* Ag, const __half* Bg,
                                        int K, int k0, int tid)
{
    int r0 = tid >> 2;             // 0..31
    int ch = (tid & 3) << 3;       // half offset in row: 0,8,16,24
    #pragma unroll
    for (int j = 0; j < 4; j++) {
        int r = r0 + 32 * j;
        uint32_t so = (uint32_t)(r * 80 + ch * 2);
        cp16s(sA + so, Ag + (size_t)r * K + k0 + ch);
        cp16s(sB + so, Bg + (size_t)r * K + k0 + ch);
    }
    asm volatile("cp.async.commit_group;" ::: "memory");
}

// ---------------- fp16 GEMM ----------------
// EPI: 1 = gelu(+bias) fp16 out, 2 = +bias+residual fp32 out, 3 = +bias fp16 out
template<int EPI>
__global__ __launch_bounds__(128)
void gemm_f16_kernel(const __half* __restrict__ A, const __half* __restrict__ Bt,
                     const float* __restrict__ bias, const float* __restrict__ res,
                     void* __restrict__ Cout, int M, int N, int K)
{
    extern __shared__ char smc[];
    uint32_t smem_base;
    asm("{ .reg .u64 t; cvta.to.shared.u64 t, %1; cvt.u32.u64 %0, t; }"
        : "=r"(smem_base) : "l"(smc));

    int tid  = threadIdx.x;
    int wid  = tid >> 5, lane = tid & 31;
    int g    = lane >> 2;
    int q    = lane & 3;
    int wm   = (wid >> 1) * 64;
    int wn   = (wid & 1) * 64;

    int row0 = blockIdx.y * 128;
    int col0 = blockIdx.x * 128;
    const __half* Ag = A  + (size_t)row0 * K;
    const __half* Bg = Bt + (size_t)col0 * K;

    float acc[4][8][4];
    #pragma unroll
    for (int mt = 0; mt < 4; mt++)
        #pragma unroll
        for (int nt = 0; nt < 8; nt++)
            #pragma unroll
            for (int r = 0; r < 4; r++) acc[mt][nt][r] = 0.f;

    const int KT = K >> 5;

    #pragma unroll
    for (int st = 0; st < 3; st++)
        gf_load(smem_base + st * GF_TILE_BYTES,
                smem_base + (GF_STAGES + st) * GF_TILE_BYTES,
                Ag, Bg, K, st * 32, tid);

    for (int kt = 0; kt < KT; kt++) {
        asm volatile("cp.async.wait_group 2;" ::: "memory");
        __syncthreads();

        if (kt + 3 < KT) {
            int st = (kt + 3) & 3;
            gf_load(smem_base + st * GF_TILE_BYTES,
                    smem_base + (GF_STAGES + st) * GF_TILE_BYTES,
                    Ag, Bg, K, (kt + 3) * 32, tid);
        }

        int st = kt & 3;
        const __half* As = (const __half*)(smc + st * GF_TILE_BYTES);
        const __half* Bs = (const __half*)(smc + (GF_STAGES + st) * GF_TILE_BYTES);

        #pragma unroll
        for (int kk = 0; kk < 32; kk += 16) {
            unsigned af[4][4];
            #pragma unroll
            for (int mt = 0; mt < 4; mt++) {
                int r = wm + mt * 16 + g;
                af[mt][0] = *(const unsigned*)(As + r * 40 + kk + 2 * q);
                af[mt][1] = *(const unsigned*)(As + (r + 8) * 40 + kk + 2 * q);
                af[mt][2] = *(const unsigned*)(As + r * 40 + kk + 2 * q + 8);
                af[mt][3] = *(const unsigned*)(As + (r + 8) * 40 + kk + 2 * q + 8);
            }
            unsigned bf[8][2];
            #pragma unroll
            for (int nt = 0; nt < 8; nt++) {
                int c = wn + nt * 8 + g;
                bf[nt][0] = *(const unsigned*)(Bs + c * 40 + kk + 2 * q);
                bf[nt][1] = *(const unsigned*)(Bs + c * 40 + kk + 2 * q + 8);
            }
            #pragma unroll
            for (int mt = 0; mt < 4; mt++)
                #pragma unroll
                for (int nt = 0; nt < 8; nt++) {
                    asm volatile(
                        "mma.sync.aligned.m16n8k16.row.col.f32.f16.f16.f32 "
                        "{%0,%1,%2,%3}, {%4,%5,%6,%7}, {%8,%9}, {%0,%1,%2,%3};"
                        : "+f"(acc[mt][nt][0]), "+f"(acc[mt][nt][1]),
                          "+f"(acc[mt][nt][2]), "+f"(acc[mt][nt][3])
                        : "r"(af[mt][0]), "r"(af[mt][1]), "r"(af[mt][2]), "r"(af[mt][3]),
                          "r"(bf[nt][0]), "r"(bf[nt][1]));
                }
        }
    }

    #pragma unroll
    for (int mt = 0; mt < 4; mt++) {
        int r = row0 + wm + mt * 16 + g;
        #pragma unroll
        for (int nt = 0; nt < 8; nt++) {
            int c = col0 + wn + nt * 8 + 2 * q;
            float bv0 = bias[c], bv1 = bias[c + 1];
            float v00 = acc[mt][nt][0] + bv0;
            float v01 = acc[mt][nt][1] + bv1;
            float v10 = acc[mt][nt][2] + bv0;
            float v11 = acc[mt][nt][3] + bv1;
            if (EPI == 1) {
                v00 = 0.5f * v00 * (1.0f + erff(v00 * 0.70710678118654752f));
                v01 = 0.5f * v01 * (1.0f + erff(v01 * 0.70710678118654752f));
                v10 = 0.5f * v10 * (1.0f + erff(v10 * 0.70710678118654752f));
                v11 = 0.5f * v11 * (1.0f + erff(v11 * 0.70710678118654752f));
            }
            if (EPI == 1 || EPI == 3) {
                __half* C = (__half*)Cout;
                *(unsigned*)(C + (size_t)r * N + c)       = packh2(v00, v01);
                *(unsigned*)(C + (size_t)(r + 8) * N + c) = packh2(v10, v11);
            } else {
                float* C = (float*)Cout;
                if (EPI == 2) {
                    float2 r0 = *(const float2*)(res + (size_t)r * N + c);
                    float2 r1 = *(const float2*)(res + (size_t)(r + 8) * N + c);
                    v00 += r0.x; v01 += r0.y;
                    v10 += r1.x; v11 += r1.y;
                }
                *(float2*)(C + (size_t)r * N + c)       = make_float2(v00, v01);
                *(float2*)(C + (size_t)(r + 8) * N + c) = make_float2(v10, v11);
            }
        }
    }
}

// ---------------- fp16 flash attention (single-buffer, hoisted Q frags) ----------------
// BQ=64, BKV=64, 4 warps, causal, GQA. Long q-tiles scheduled first (reversed qt).
__global__ __launch_bounds__(128)
void attn_f16_kernel(const __half* __restrict__ Q, const __half* __restrict__ K,
                     const __half* __restrict__ V, __half* __restrict__ O)
{
    __shared__ __half Qs[64][72];
    __shared__ __half Ks[64][72];
    __shared__ __half Vs[64][72];

    int tid  = threadIdx.x;
    int wid  = tid >> 5, lane = tid & 31;
    int g    = lane >> 2;
    int q    = lane & 3;
    int qt   = gridDim.x - 1 - blockIdx.x;   // longest-job-first
    int bh   = blockIdx.y;
    int b    = bh >> 4;
    int h    = bh & 15;
    int kvh  = h >> 2;
    int q0   = qt * 64;

    const __half* Qb = Q + (size_t)(b * NHEAD + h)  * S_LEN * 64 + (size_t)q0 * 64;
    const __half* Kb = K + (size_t)(b * NKV  + kvh) * S_LEN * 64;
    const __half* Vb = V + (size_t)(b * NKV  + kvh) * S_LEN * 64;

    // stage Q: 64 rows x 64 halves (8x uint4 per row)
    for (int i = tid; i < 64 * 8; i += 128) {
        int r = i >> 3, c = (i & 7) * 8;
        *(uint4*)&Qs[r][c] = *(const uint4*)(Qb + (size_t)r * 64 + c);
    }
    __syncthreads();

    // hoist Q fragments (loop-invariant across kv tiles)
    int row_a = 16 * wid + g;
    unsigned qa[4][4];
    #pragma unroll
    for (int c4 = 0; c4 < 4; c4++) {
        int kk = c4 * 16;
        qa[c4][0] = *(const unsigned*)&Qs[row_a][kk + 2 * q];
        qa[c4][1] = *(const unsigned*)&Qs[row_a + 8][kk + 2 * q];
        qa[c4][2] = *(const unsigned*)&Qs[row_a][kk + 2 * q + 8];
        qa[c4][3] = *(const unsigned*)&Qs[row_a + 8][kk + 2 * q + 8];
    }

    float m0 = -INFINITY, m1 = -INFINITY, l0 = 0.f, l1 = 0.f;
    float o[8][4];
    #pragma unroll
    for (int nt = 0; nt < 8; nt++)
        #pragma unroll
        for (int r = 0; r < 4; r++) o[nt][r] = 0.f;

    int nkt = qt + 1;
    int vmat = lane >> 3;          // 0..3
    int vrow = lane & 7;           // 0..7

    for (int jt = 0; jt < nkt; ++jt) {
        int j0 = jt * 64;
        __syncthreads();
        for (int i = tid; i < 64 * 8; i += 128) {
            int r = i >> 3, c = (i & 7) * 8;
            *(uint4*)&Ks[r][c] = *(const uint4*)(Kb + (size_t)(j0 + r) * 64 + c);
            *(uint4*)&Vs[r][c] = *(const uint4*)(Vb + (size_t)(j0 + r) * 64 + c);
        }
        __syncthreads();

        // ---- S = Q K^T ----
        float s[8][4];
        #pragma unroll
        for (int nt = 0; nt < 8; nt++)
            #pragma unroll
            for (int r = 0; r < 4; r++) s[nt][r] = 0.f;

        #pragma unroll
        for (int c4 = 0; c4 < 4; c4++) {
            int kk = c4 * 16;
            #pragma unroll
            for (int nt = 0; nt < 8; nt++) {
                unsigned b0 = *(const unsigned*)&Ks[nt * 8 + g][kk + 2 * q];
                unsigned b1 = *(const unsigned*)&Ks[nt * 8 + g][kk + 2 * q + 8];
                asm volatile(
                    "mma.sync.aligned.m16n8k16.row.col.f32.f16.f16.f32 "
                    "{%0,%1,%2,%3}, {%4,%5,%6,%7}, {%8,%9}, {%0,%1,%2,%3};"
                    : "+f"(s[nt][0]), "+f"(s[nt][1]), "+f"(s[nt][2]), "+f"(s[nt][3])
                    : "r"(qa[c4][0]), "r"(qa[c4][1]), "r"(qa[c4][2]), "r"(qa[c4][3]),
                      "r"(b0), "r"(b1));
            }
        }

        // ---- causal mask (diagonal tile only) ----
        if (jt == qt) {
            #pragma unroll
            for (int nt = 0; nt < 8; nt++) {
                int col = nt * 8 + 2 * q;
                if (col     > row_a)     s[nt][0] = -INFINITY;
                if (col + 1 > row_a)     s[nt][1] = -INFINITY;
                if (col     > row_a + 8) s[nt][2] = -INFINITY;
                if (col + 1 > row_a + 8) s[nt][3] = -INFINITY;
            }
        }

        // ---- online softmax ----
        float mt0 = -INFINITY, mt1 = -INFINITY;
        #pragma unroll
        for (int nt = 0; nt < 8; nt++) {
            mt0 = fmaxf(mt0, fmaxf(s[nt][0], s[nt][1]));
            mt1 = fmaxf(mt1, fmaxf(s[nt][2], s[nt][3]));
        }
        #pragma unroll
        for (int off = 1; off < 4; off <<= 1) {
            mt0 = fmaxf(mt0, __shfl_xor_sync(0xffffffffu, mt0, off));
            mt1 = fmaxf(mt1, __shfl_xor_sync(0xffffffffu, mt1, off));
        }
        float mn0 = fmaxf(m0, mt0), mn1 = fmaxf(m1, mt1);
        float al0 = __expf(m0 - mn0), al1 = __expf(m1 - mn1);
        m0 = mn0; m1 = mn1;
        float ps0 = 0.f, ps1 = 0.f;
        #pragma unroll
        for (int nt = 0; nt < 8; nt++) {
            s[nt][0] = __expf(s[nt][0] - mn0);
            s[nt][1] = __expf(s[nt][1] - mn0);
            s[nt][2] = __expf(s[nt][2] - mn1);
            s[nt][3] = __expf(s[nt][3] - mn1);
            ps0 += s[nt][0] + s[nt][1];
            ps1 += s[nt][2] + s[nt][3];
            o[nt][0] *= al0; o[nt][1] *= al0;
            o[nt][2] *= al1; o[nt][3] *= al1;
        }
        #pragma unroll
        for (int off = 1; off < 4; off <<= 1) {
            ps0 += __shfl_xor_sync(0xffffffffu, ps0, off);
            ps1 += __shfl_xor_sync(0xffffffffu, ps1, off);
        }
        l0 = l0 * al0 + ps0;
        l1 = l1 * al1 + ps1;

        // ---- O += P V : C-frag of S -> A-frag directly; V via ldmatrix.trans ----
        #pragma unroll
        for (int kc = 0; kc < 4; kc++) {
            unsigned a0 = packh2(s[2 * kc][0],     s[2 * kc][1]);
            unsigned a1 = packh2(s[2 * kc][2],     s[2 * kc][3]);
            unsigned a2 = packh2(s[2 * kc + 1][0], s[2 * kc + 1][1]);
            unsigned a3 = packh2(s[2 * kc + 1][2], s[2 * kc + 1][3]);
            #pragma unroll
            for (int ntp = 0; ntp < 4; ntp++) {
                const __half* vp = &Vs[kc * 16 + (vmat & 1) * 8 + vrow]
                                      [ntp * 16 + (vmat >> 1) * 8];
                uint32_t vaddr = (uint32_t)__cvta_generic_to_shared(vp);
                unsigned v0, v1, v2, v3;
                asm volatile(
                    "ldmatrix.sync.aligned.m8n8.x4.trans.shared.b16 {%0,%1,%2,%3}, [%4];"
                    : "=r"(v0), "=r"(v1), "=r"(v2), "=r"(v3) : "r"(vaddr));
                asm volatile(
                    "mma.sync.aligned.m16n8k16.row.col.f32.f16.f16.f32 "
                    "{%0,%1,%2,%3}, {%4,%5,%6,%7}, {%8,%9}, {%0,%1,%2,%3};"
                    : "+f"(o[2 * ntp][0]), "+f"(o[2 * ntp][1]),
                      "+f"(o[2 * ntp][2]), "+f"(o[2 * ntp][3])
                    : "r"(a0), "r"(a1), "r"(a2), "r"(a3), "r"(v0), "r"(v1));
                asm volatile(
                    "mma.sync.aligned.m16n8k16.row.col.f32.f16.f16.f32 "
                    "{%0,%1,%2,%3}, {%4,%5,%6,%7}, {%8,%9}, {%0,%1,%2,%3};"
                    : "+f"(o[2 * ntp + 1][0]), "+f"(o[2 * ntp + 1][1]),
                      "+f"(o[2 * ntp + 1][2]), "+f"(o[2 * ntp + 1][3])
                    : "r"(a0), "r"(a1), "r"(a2), "r"(a3), "r"(v2), "r"(v3));
            }
        }
    }

    // ---- epilogue: normalize, write fp16 [token, D] ----
    float inv0 = 1.0f / l0, inv1 = 1.0f / l1;
    int srow0 = q0 + row_a;
    int srow1 = srow0 + 8;
    #pragma unroll
    for (int nt = 0; nt < 8; nt++) {
        int c = h * 64 + nt * 8 + 2 * q;
        *(unsigned*)(O + ((size_t)srow0 * BATCH + b) * DMODEL + c) =
            packh2(o[nt][0] * inv0, o[nt][1] * inv0);
        *(unsigned*)(O + ((size_t)srow1 * BATCH + b) * DMODEL + c) =
            packh2(o[nt][2] * inv1, o[nt][3] * inv1);
    }
}

// ---------------- host orchestration ----------------
extern "C" void kernel_launch(void* const* d_in, const int* in_sizes, int n_in,
                              void* d_out, int out_size)
{
    const float* x   = (const float*)d_in[0];
    const float* n1w = (const float*)d_in[1];
    const float* wq  = (const float*)d_in[2];
    const float* bq  = (const float*)d_in[3];
    const float* wk  = (const float*)d_in[4];
    const float* bk  = (const float*)d_in[5];
    const float* wv  = (const float*)d_in[6];
    const float* bv  = (const float*)d_in[7];
    const float* qnw = (const float*)d_in[8];
    const float* knw = (const float*)d_in[9];
    const float* wo  = (const float*)d_in[10];
    const float* bo  = (const float*)d_in[11];
    const float* n2w = (const float*)d_in[12];
    const float* w1  = (const float*)d_in[13];
    const float* b1  = (const float*)d_in[14];
    const float* w2  = (const float*)d_in[15];
    const float* b2  = (const float*)d_in[16];

    __half *ph, *pwqkv, *pqkv, *pattn, *ph2, *pmid, *pwor, *pw1r, *pw2r, *pq, *pk, *pv;
    float *pbqkv, *px1;
    cudaGetSymbolAddress((void**)&ph,    g_h);
    cudaGetSymbolAddress((void**)&pwqkv, g_wqkv);
    cudaGetSymbolAddress((void**)&pbqkv, g_bqkv);
    cudaGetSymbolAddress((void**)&pqkv,  g_qkv);
    cudaGetSymbolAddress((void**)&pq,    g_q);
    cudaGetSymbolAddress((void**)&pk,    g_k);
    cudaGetSymbolAddress((void**)&pv,    g_v);
    cudaGetSymbolAddress((void**)&pattn, g_attn);
    cudaGetSymbolAddress((void**)&px1,   g_x1);
    cudaGetSymbolAddress((void**)&ph2,   g_h2);
    cudaGetSymbolAddress((void**)&pmid,  g_mid);
    cudaGetSymbolAddress((void**)&pwor,  g_wor);
    cudaGetSymbolAddress((void**)&pw1r,  g_w1r);
    cudaGetSymbolAddress((void**)&pw2r,  g_w2r);

    cudaFuncSetAttribute(gemm_f16_kernel<1>,
                         cudaFuncAttributeMaxDynamicSharedMemorySize, GF_SMEM_BYTES);
    cudaFuncSetAttribute(gemm_f16_kernel<2>,
                         cudaFuncAttributeMaxDynamicSharedMemorySize, GF_SMEM_BYTES);
    cudaFuncSetAttribute(gemm_f16_kernel<3>,
                         cudaFuncAttributeMaxDynamicSharedMemorySize, GF_SMEM_BYTES);

    // all weight prep in one launch
    prep_kernel<<<PREP_TOTAL, 256>>>(wq, wk, wv, bq, bk, bv, wo, w1, w2,
                                     pwqkv, pbqkv, pwor, pw1r, pw2r);

    rmsnorm_kernel<<<NTOK, 256>>>(x, n1w, ph);
    gemm_f16_kernel<3><<<dim3(QKVN / 128, NTOK / 128), 128, GF_SMEM_BYTES>>>(
        ph, pwqkv, pbqkv, nullptr, pqkv, NTOK, QKVN, DMODEL);
    qkrope_kernel<<<dim3(NTOK, 6), dim3(64, 4)>>>(pqkv, qnw, knw, pq, pk, pv);
    attn_f16_kernel<<<dim3(S_LEN / 64, BATCH * NHEAD), 128>>>(pq, pk, pv, pattn);
    gemm_f16_kernel<2><<<dim3(DMODEL / 128, NTOK / 128), 128, GF_SMEM_BYTES>>>(
        pattn, pwor, bo, x, px1, NTOK, DMODEL, DMODEL);
    rmsnorm_kernel<<<NTOK, 256>>>(px1, n2w, ph2);
    gemm_f16_kernel<1><<<dim3(DFF / 128, NTOK / 128), 128, GF_SMEM_BYTES>>>(
        ph2, pw1r, b1, nullptr, pmid, NTOK, DFF, DMODEL);
    gemm_f16_kernel<2><<<dim3(DMODEL / 128, NTOK / 128), 128, GF_SMEM_BYTES>>>(
        pmid, pw2r, b2, px1, d_out, NTOK, DMODEL, DFF);
}

// round 15
// speedup vs baseline: 1.0465x; 1.0086x over previous
#include <cuda_runtime.h>
#include <cuda_fp16.h>
#include <math.h>
#include <stdint.h>

#define S_LEN   2048
#define BATCH   2
#define DMODEL  1024
#define NHEAD   16
#define NKV     4
#define HEADDIM 64
#define NTOK    4096            // S_LEN * BATCH
#define DFF     4096            // 4 * DMODEL
#define QKVN    1536            // 1024 + 256 + 256
#define EPS_F   1e-5f
#define QK_SCALE 0.03125f       // D^-0.5 = 1/32

// fp16 GEMM smem: 4 stages, tiles [128 rows][40 halfs] (stride 80B)
#define GF_TILE_BYTES 10240     // 128*80
#define GF_STAGES 4
#define GF_SMEM_BYTES (2 * GF_STAGES * GF_TILE_BYTES)   // 81920

// fused prep grid ranges (32x32 tiles) + rope table
#define PREP_QKV_BLKS   (48 * 32)          // 1536
#define PREP_WO_BLKS    (32 * 32)          // 1024
#define PREP_W1_BLKS    (128 * 32)         // 4096
#define PREP_W2_BLKS    (32 * 128)         // 4096
#define PREP_ROPE_BLKS  (S_LEN * 32 / 256) // 256
#define PREP_TOTAL (PREP_QKV_BLKS + PREP_WO_BLKS + PREP_W1_BLKS + PREP_W2_BLKS + PREP_ROPE_BLKS)

// ---------------- scratch (__device__ globals; no allocation allowed) ----------------
__device__ __half g_h   [NTOK * DMODEL];
__device__ __half g_wqkv[QKVN * DMODEL];      // transposed [N,K]
__device__ float  g_bqkv[QKVN];
__device__ __half g_qkv [NTOK * QKVN];
__device__ __half g_q   [BATCH * NHEAD * S_LEN * HEADDIM];
__device__ __half g_k   [BATCH * NKV   * S_LEN * HEADDIM];
__device__ __half g_v   [BATCH * NKV   * S_LEN * HEADDIM];
__device__ __half g_attn[NTOK * DMODEL];
__device__ float  g_x1  [NTOK * DMODEL];
__device__ __half g_h2  [NTOK * DMODEL];
__device__ __half g_mid [NTOK * DFF];
__device__ __half g_wor [DMODEL * DMODEL];    // transposed
__device__ __half g_w1r [DFF * DMODEL];       // transposed
__device__ __half g_w2r [DMODEL * DFF];       // transposed
__device__ float2 g_rope[S_LEN * 32];         // (cos, sin) per (s, j)

__device__ __forceinline__ void cp16s(uint32_t daddr, const void* src) {
    asm volatile("cp.async.ca.shared.global [%0], [%1], 16;" :: "r"(daddr), "l"(src));
}
__device__ __forceinline__ unsigned packh2(float a, float b) {
    __half2 h = __floats2half2_rn(a, b);
    return *(unsigned*)&h;
}

// ---------------- fused weight prep + rope table, one launch --------
__device__ __forceinline__ void tile_transpose(const float* __restrict__ src,
                                               __half* __restrict__ dst,
                                               int R, int C, int bx, int by, int tx, int ty)
{
    __shared__ float t[32][33];
    #pragma unroll
    for (int j = 0; j < 4; j++)
        t[ty + 8 * j][tx] = src[(size_t)(by + ty + 8 * j) * C + bx + tx];
    __syncthreads();
    #pragma unroll
    for (int j = 0; j < 4; j++)
        dst[(size_t)(bx + ty + 8 * j) * R + by + tx] = __float2half_rn(t[tx][ty + 8 * j]);
}

__global__ __launch_bounds__(256)
void prep_kernel(const float* __restrict__ wq, const float* __restrict__ wk,
                 const float* __restrict__ wv, const float* __restrict__ bq,
                 const float* __restrict__ bk, const float* __restrict__ bv,
                 const float* __restrict__ wo, const float* __restrict__ w1,
                 const float* __restrict__ w2,
                 __half* __restrict__ Wqkv, float* __restrict__ bias,
                 __half* __restrict__ Wor, __half* __restrict__ W1r,
                 __half* __restrict__ W2r, float2* __restrict__ rope)
{
    int blk = blockIdx.x;
    int tx = threadIdx.x & 31;
    int ty = threadIdx.x >> 5;

    if (blk < PREP_QKV_BLKS) {
        __shared__ float t[32][33];
        int bx = (blk % 48) * 32;   // c base
        int by = (blk / 48) * 32;   // k base
        #pragma unroll
        for (int j = 0; j < 4; j++) {
            int k = by + ty + 8 * j;
            int c = bx + tx;
            float v;
            if (c < 1024)       v = wq[(size_t)k * 1024 + c];
            else if (c < 1280)  v = wk[(size_t)k * 256 + (c - 1024)];
            else                v = wv[(size_t)k * 256 + (c - 1280)];
            t[ty + 8 * j][tx] = v;
        }
        __syncthreads();
        #pragma unroll
        for (int j = 0; j < 4; j++) {
            int c = bx + ty + 8 * j;
            Wqkv[(size_t)c * DMODEL + by + tx] = __float2half_rn(t[tx][ty + 8 * j]);
        }
        if (blk < 6) {
            int i = blk * 256 + threadIdx.x;
            if (i < QKVN)
                bias[i] = (i < 1024) ? bq[i] : (i < 1280 ? bk[i - 1024] : bv[i - 1280]);
        }
        return;
    }
    blk -= PREP_QKV_BLKS;
    if (blk < PREP_WO_BLKS) {
        tile_transpose(wo, Wor, DMODEL, DMODEL, (blk % 32) * 32, (blk / 32) * 32, tx, ty);
        return;
    }
    blk -= PREP_WO_BLKS;
    if (blk < PREP_W1_BLKS) {
        tile_transpose(w1, W1r, DMODEL, DFF, (blk % 128) * 32, (blk / 128) * 32, tx, ty);
        return;
    }
    blk -= PREP_W1_BLKS;
    if (blk < PREP_W2_BLKS) {
        tile_transpose(w2, W2r, DFF, DMODEL, (blk % 32) * 32, (blk / 32) * 32, tx, ty);
        return;
    }
    blk -= PREP_W2_BLKS;
    // rope table: idx -> (s, j)
    int idx = blk * 256 + threadIdx.x;
    int s = idx >> 5, j = idx & 31;
    float invf = exp2f(-(float)j * (13.287712379549449f / 32.0f));
    float ang = (float)s * invf;
    float sn, cs;
    sincosf(ang, &sn, &cs);
    rope[idx] = make_float2(cs, sn);
}

// ---------------- RMSNorm over D=1024, fp16 output ----------------
__global__ __launch_bounds__(256)
void rmsnorm_kernel(const float* __restrict__ x, const float* __restrict__ w,
                    __half* __restrict__ y)
{
    int row = blockIdx.x;
    int i = threadIdx.x;
    const float* xr = x + (size_t)row * DMODEL;
    float4 xv = *(const float4*)(xr + i * 4);
    float ss = xv.x * xv.x + xv.y * xv.y + xv.z * xv.z + xv.w * xv.w;
    #pragma unroll
    for (int off = 16; off; off >>= 1) ss += __shfl_xor_sync(0xffffffffu, ss, off);
    __shared__ float red[8];
    __shared__ float s_sc;
    if ((i & 31) == 0) red[i >> 5] = ss;
    __syncthreads();
    if (i == 0) {
        float tot = 0.f;
        #pragma unroll
        for (int kk = 0; kk < 8; kk++) tot += red[kk];
        s_sc = rsqrtf(tot * (1.0f / DMODEL) + EPS_F);
    }
    __syncthreads();
    float sc = s_sc;
    float4 wv = *(const float4*)(w + i * 4);
    uint2 u;
    u.x = packh2(xv.x * sc * wv.x, xv.y * sc * wv.y);
    u.y = packh2(xv.z * sc * wv.z, xv.w * sc * wv.w);
    *(uint2*)(y + (size_t)row * DMODEL + i * 4) = u;
}

// ---------------- per-head QK RMSNorm + RoPE (table) + relayout ----------------
__global__ __launch_bounds__(256)
void qkrope_kernel(const __half* __restrict__ qkv, const float* __restrict__ qn_w,
                   const float* __restrict__ kn_w, const float2* __restrict__ rope,
                   __half* __restrict__ Qo, __half* __restrict__ Ko,
                   __half* __restrict__ Vo)
{
    int t = blockIdx.x;            // token = s*BATCH + b
    int ty = threadIdx.y;          // 0..3
    int slot = blockIdx.y * 4 + ty;
    int i = threadIdx.x;           // 0..63
    int s = t / BATCH, b = t % BATCH;
    __shared__ float buf[4][64];
    __shared__ float red[4][2];

    if (slot >= 20) {   // V: pure relayout (whole block is V)
        int vh = slot - 20;
        Vo[((size_t)(b * NKV + vh) * S_LEN + s) * 64 + i] =
            qkv[(size_t)t * QKVN + 1280 + vh * 64 + i];
        return;
    }

    bool is_q = (slot < 16);
    int col = is_q ? (slot * 64 + i) : (1024 + (slot - 16) * 64 + i);
    float v = __half2float(qkv[(size_t)t * QKVN + col]);
    float ss = v * v;
    #pragma unroll
    for (int off = 16; off; off >>= 1) ss += __shfl_xor_sync(0xffffffffu, ss, off);
    if ((i & 31) == 0) red[ty][i >> 5] = ss;
    __syncthreads();
    float tot = red[ty][0] + red[ty][1];
    float sc = rsqrtf(tot * (1.0f / 64.0f) + EPS_F);
    const float* w = is_q ? qn_w : kn_w;
    float nv = v * sc * w[i];
    buf[ty][i] = nv;
    __syncthreads();
    float rot = (i < 32) ? -buf[ty][i + 32] : buf[ty][i - 32];
    float2 cs2 = rope[(size_t)s * 32 + (i & 31)];
    float outv = nv * cs2.x + rot * cs2.y;
    if (is_q) {
        outv *= QK_SCALE;
        Qo[((size_t)(b * NHEAD + slot) * S_LEN + s) * 64 + i] = __float2half_rn(outv);
    } else {
        Ko[((size_t)(b * NKV + (slot - 16)) * S_LEN + s) * 64 + i] = __float2half_rn(outv);
    }
}

// ---------------- fp16 GEMM stage loader: 8 cp.async per thread ----------------
__device__ __forceinline__ void gf_load(uint32_t sA, uint32_t sB,
                                        const __half* Ag, const __half* Bg,
                                        int K, int k0, int tid)
{
    int r0 = tid >> 2;             // 0..31
    int ch = (tid & 3) << 3;       // half offset in row: 0,8,16,24
    #pragma unroll
    for (int j = 0; j < 4; j++) {
        int r = r0 + 32 * j;
        uint32_t so = (uint32_t)(r * 80 + ch * 2);
        cp16s(sA + so, Ag + (size_t)r * K + k0 + ch);
        cp16s(sB + so, Bg + (size_t)r * K + k0 + ch);
    }
    asm volatile("cp.async.commit_group;" ::: "memory");
}

// ---------------- fp16 GEMM ----------------
// EPI: 1 = gelu(+bias) fp16 out, 2 = +bias+residual fp32 out, 3 = +bias fp16 out
template<int EPI>
__global__ __launch_bounds__(128)
void gemm_f16_kernel(const __half* __restrict__ A, const __half* __restrict__ Bt,
                     const float* __restrict__ bias, const float* __restrict__ res,
                     void* __restrict__ Cout, int M, int N, int K)
{
    extern __shared__ char smc[];
    uint32_t smem_base;
    asm("{ .reg .u64 t; cvta.to.shared.u64 t, %1; cvt.u32.u64 %0, t; }"
        : "=r"(smem_base) : "l"(smc));

    int tid  = threadIdx.x;
    int wid  = tid >> 5, lane = tid & 31;
    int g    = lane >> 2;
    int q    = lane & 3;
    int wm   = (wid >> 1) * 64;
    int wn   = (wid & 1) * 64;

    int row0 = blockIdx.y * 128;
    int col0 = blockIdx.x * 128;
    const __half* Ag = A  + (size_t)row0 * K;
    const __half* Bg = Bt + (size_t)col0 * K;

    float acc[4][8][4];
    #pragma unroll
    for (int mt = 0; mt < 4; mt++)
        #pragma unroll
        for (int nt = 0; nt < 8; nt++)
            #pragma unroll
            for (int r = 0; r < 4; r++) acc[mt][nt][r] = 0.f;

    const int KT = K >> 5;

    #pragma unroll
    for (int st = 0; st < 3; st++)
        gf_load(smem_base + st * GF_TILE_BYTES,
                smem_base + (GF_STAGES + st) * GF_TILE_BYTES,
                Ag, Bg, K, st * 32, tid);

    for (int kt = 0; kt < KT; kt++) {
        asm volatile("cp.async.wait_group 2;" ::: "memory");
        __syncthreads();

        if (kt + 3 < KT) {
            int st = (kt + 3) & 3;
            gf_load(smem_base + st * GF_TILE_BYTES,
                    smem_base + (GF_STAGES + st) * GF_TILE_BYTES,
                    Ag, Bg, K, (kt + 3) * 32, tid);
        }

        int st = kt & 3;
        const __half* As = (const __half*)(smc + st * GF_TILE_BYTES);
        const __half* Bs = (const __half*)(smc + (GF_STAGES + st) * GF_TILE_BYTES);

        #pragma unroll
        for (int kk = 0; kk < 32; kk += 16) {
            unsigned af[4][4];
            #pragma unroll
            for (int mt = 0; mt < 4; mt++) {
                int r = wm + mt * 16 + g;
                af[mt][0] = *(const unsigned*)(As + r * 40 + kk + 2 * q);
                af[mt][1] = *(const unsigned*)(As + (r + 8) * 40 + kk + 2 * q);
                af[mt][2] = *(const unsigned*)(As + r * 40 + kk + 2 * q + 8);
                af[mt][3] = *(const unsigned*)(As + (r + 8) * 40 + kk + 2 * q + 8);
            }
            unsigned bf[8][2];
            #pragma unroll
            for (int nt = 0; nt < 8; nt++) {
                int c = wn + nt * 8 + g;
                bf[nt][0] = *(const unsigned*)(Bs + c * 40 + kk + 2 * q);
                bf[nt][1] = *(const unsigned*)(Bs + c * 40 + kk + 2 * q + 8);
            }
            #pragma unroll
            for (int mt = 0; mt < 4; mt++)
                #pragma unroll
                for (int nt = 0; nt < 8; nt++) {
                    asm volatile(
                        "mma.sync.aligned.m16n8k16.row.col.f32.f16.f16.f32 "
                        "{%0,%1,%2,%3}, {%4,%5,%6,%7}, {%8,%9}, {%0,%1,%2,%3};"
                        : "+f"(acc[mt][nt][0]), "+f"(acc[mt][nt][1]),
                          "+f"(acc[mt][nt][2]), "+f"(acc[mt][nt][3])
                        : "r"(af[mt][0]), "r"(af[mt][1]), "r"(af[mt][2]), "r"(af[mt][3]),
                          "r"(bf[nt][0]), "r"(bf[nt][1]));
                }
        }
    }

    #pragma unroll
    for (int mt = 0; mt < 4; mt++) {
        int r = row0 + wm + mt * 16 + g;
        #pragma unroll
        for (int nt = 0; nt < 8; nt++) {
            int c = col0 + wn + nt * 8 + 2 * q;
            float bv0 = bias[c], bv1 = bias[c + 1];
            float v00 = acc[mt][nt][0] + bv0;
            float v01 = acc[mt][nt][1] + bv1;
            float v10 = acc[mt][nt][2] + bv0;
            float v11 = acc[mt][nt][3] + bv1;
            if (EPI == 1) {
                v00 = 0.5f * v00 * (1.0f + erff(v00 * 0.70710678118654752f));
                v01 = 0.5f * v01 * (1.0f + erff(v01 * 0.70710678118654752f));
                v10 = 0.5f * v10 * (1.0f + erff(v10 * 0.70710678118654752f));
                v11 = 0.5f * v11 * (1.0f + erff(v11 * 0.70710678118654752f));
            }
            if (EPI == 1 || EPI == 3) {
                __half* C = (__half*)Cout;
                *(unsigned*)(C + (size_t)r * N + c)       = packh2(v00, v01);
                *(unsigned*)(C + (size_t)(r + 8) * N + c) = packh2(v10, v11);
            } else {
                float* C = (float*)Cout;
                if (EPI == 2) {
                    float2 r0 = *(const float2*)(res + (size_t)r * N + c);
                    float2 r1 = *(const float2*)(res + (size_t)(r + 8) * N + c);
                    v00 += r0.x; v01 += r0.y;
                    v10 += r1.x; v11 += r1.y;
                }
                *(float2*)(C + (size_t)r * N + c)       = make_float2(v00, v01);
                *(float2*)(C + (size_t)(r + 8) * N + c) = make_float2(v10, v11);
            }
        }
    }
}

// ---------------- fp16 flash attention (single-buffer, hoisted Q frags, LJF) ----------
__global__ __launch_bounds__(128)
void attn_f16_kernel(const __half* __restrict__ Q, const __half* __restrict__ K,
                     const __half* __restrict__ V, __half* __restrict__ O)
{
    __shared__ __half Qs[64][72];
    __shared__ __half Ks[64][72];
    __shared__ __half Vs[64][72];

    int tid  = threadIdx.x;
    int wid  = tid >> 5, lane = tid & 31;
    int g    = lane >> 2;
    int q    = lane & 3;
    int qt   = gridDim.x - 1 - blockIdx.x;   // longest-job-first
    int bh   = blockIdx.y;
    int b    = bh >> 4;
    int h    = bh & 15;
    int kvh  = h >> 2;
    int q0   = qt * 64;

    const __half* Qb = Q + (size_t)(b * NHEAD + h)  * S_LEN * 64 + (size_t)q0 * 64;
    const __half* Kb = K + (size_t)(b * NKV  + kvh) * S_LEN * 64;
    const __half* Vb = V + (size_t)(b * NKV  + kvh) * S_LEN * 64;

    for (int i = tid; i < 64 * 8; i += 128) {
        int r = i >> 3, c = (i & 7) * 8;
        *(uint4*)&Qs[r][c] = *(const uint4*)(Qb + (size_t)r * 64 + c);
    }
    __syncthreads();

    int row_a = 16 * wid + g;
    unsigned qa[4][4];
    #pragma unroll
    for (int c4 = 0; c4 < 4; c4++) {
        int kk = c4 * 16;
        qa[c4][0] = *(const unsigned*)&Qs[row_a][kk + 2 * q];
        qa[c4][1] = *(const unsigned*)&Qs[row_a + 8][kk + 2 * q];
        qa[c4][2] = *(const unsigned*)&Qs[row_a][kk + 2 * q + 8];
        qa[c4][3] = *(const unsigned*)&Qs[row_a + 8][kk + 2 * q + 8];
    }

    float m0 = -INFINITY, m1 = -INFINITY, l0 = 0.f, l1 = 0.f;
    float o[8][4];
    #pragma unroll
    for (int nt = 0; nt < 8; nt++)
        #pragma unroll
        for (int r = 0; r < 4; r++) o[nt][r] = 0.f;

    int nkt = qt + 1;
    int vmat = lane >> 3;
    int vrow = lane & 7;

    for (int jt = 0; jt < nkt; ++jt) {
        int j0 = jt * 64;
        __syncthreads();
        for (int i = tid; i < 64 * 8; i += 128) {
            int r = i >> 3, c = (i & 7) * 8;
            *(uint4*)&Ks[r][c] = *(const uint4*)(Kb + (size_t)(j0 + r) * 64 + c);
            *(uint4*)&Vs[r][c] = *(const uint4*)(Vb + (size_t)(j0 + r) * 64 + c);
        }
        __syncthreads();

        float s[8][4];
        #pragma unroll
        for (int nt = 0; nt < 8; nt++)
            #pragma unroll
            for (int r = 0; r < 4; r++) s[nt][r] = 0.f;

        #pragma unroll
        for (int c4 = 0; c4 < 4; c4++) {
            int kk = c4 * 16;
            #pragma unroll
            for (int nt = 0; nt < 8; nt++) {
                unsigned b0 = *(const unsigned*)&Ks[nt * 8 + g][kk + 2 * q];
                unsigned b1 = *(const unsigned*)&Ks[nt * 8 + g][kk + 2 * q + 8];
                asm volatile(
                    "mma.sync.aligned.m16n8k16.row.col.f32.f16.f16.f32 "
                    "{%0,%1,%2,%3}, {%4,%5,%6,%7}, {%8,%9}, {%0,%1,%2,%3};"
                    : "+f"(s[nt][0]), "+f"(s[nt][1]), "+f"(s[nt][2]), "+f"(s[nt][3])
                    : "r"(qa[c4][0]), "r"(qa[c4][1]), "r"(qa[c4][2]), "r"(qa[c4][3]),
                      "r"(b0), "r"(b1));
            }
        }

        if (jt == qt) {
            #pragma unroll
            for (int nt = 0; nt < 8; nt++) {
                int col = nt * 8 + 2 * q;
                if (col     > row_a)     s[nt][0] = -INFINITY;
                if (col + 1 > row_a)     s[nt][1] = -INFINITY;
                if (col     > row_a + 8) s[nt][2] = -INFINITY;
                if (col + 1 > row_a + 8) s[nt][3] = -INFINITY;
            }
        }

        float mt0 = -INFINITY, mt1 = -INFINITY;
        #pragma unroll
        for (int nt = 0; nt < 8; nt++) {
            mt0 = fmaxf(mt0, fmaxf(s[nt][0], s[nt][1]));
            mt1 = fmaxf(mt1, fmaxf(s[nt][2], s[nt][3]));
        }
        #pragma unroll
        for (int off = 1; off < 4; off <<= 1) {
            mt0 = fmaxf(mt0, __shfl_xor_sync(0xffffffffu, mt0, off));
            mt1 = fmaxf(mt1, __shfl_xor_sync(0xffffffffu, mt1, off));
        }
        float mn0 = fmaxf(m0, mt0), mn1 = fmaxf(m1, mt1);
        float al0 = __expf(m0 - mn0), al1 = __expf(m1 - mn1);
        m0 = mn0; m1 = mn1;
        float ps0 = 0.f, ps1 = 0.f;
        #pragma unroll
        for (int nt = 0; nt < 8; nt++) {
            s[nt][0] = __expf(s[nt][0] - mn0);
            s[nt][1] = __expf(s[nt][1] - mn0);
            s[nt][2] = __expf(s[nt][2] - mn1);
            s[nt][3] = __expf(s[nt][3] - mn1);
            ps0 += s[nt][0] + s[nt][1];
            ps1 += s[nt][2] + s[nt][3];
            o[nt][0] *= al0; o[nt][1] *= al0;
            o[nt][2] *= al1; o[nt][3] *= al1;
        }
        #pragma unroll
        for (int off = 1; off < 4; off <<= 1) {
            ps0 += __shfl_xor_sync(0xffffffffu, ps0, off);
            ps1 += __shfl_xor_sync(0xffffffffu, ps1, off);
        }
        l0 = l0 * al0 + ps0;
        l1 = l1 * al1 + ps1;

        #pragma unroll
        for (int kc = 0; kc < 4; kc++) {
            unsigned a0 = packh2(s[2 * kc][0],     s[2 * kc][1]);
            unsigned a1 = packh2(s[2 * kc][2],     s[2 * kc][3]);
            unsigned a2 = packh2(s[2 * kc + 1][0], s[2 * kc + 1][1]);
            unsigned a3 = packh2(s[2 * kc + 1][2], s[2 * kc + 1][3]);
            #pragma unroll
            for (int ntp = 0; ntp < 4; ntp++) {
                const __half* vp = &Vs[kc * 16 + (vmat & 1) * 8 + vrow]
                                      [ntp * 16 + (vmat >> 1) * 8];
                uint32_t vaddr = (uint32_t)__cvta_generic_to_shared(vp);
                unsigned v0, v1, v2, v3;
                asm volatile(
                    "ldmatrix.sync.aligned.m8n8.x4.trans.shared.b16 {%0,%1,%2,%3}, [%4];"
                    : "=r"(v0), "=r"(v1), "=r"(v2), "=r"(v3) : "r"(vaddr));
                asm volatile(
                    "mma.sync.aligned.m16n8k16.row.col.f32.f16.f16.f32 "
                    "{%0,%1,%2,%3}, {%4,%5,%6,%7}, {%8,%9}, {%0,%1,%2,%3};"
                    : "+f"(o[2 * ntp][0]), "+f"(o[2 * ntp][1]),
                      "+f"(o[2 * ntp][2]), "+f"(o[2 * ntp][3])
                    : "r"(a0), "r"(a1), "r"(a2), "r"(a3), "r"(v0), "r"(v1));
                asm volatile(
                    "mma.sync.aligned.m16n8k16.row.col.f32.f16.f16.f32 "
                    "{%0,%1,%2,%3}, {%4,%5,%6,%7}, {%8,%9}, {%0,%1,%2,%3};"
                    : "+f"(o[2 * ntp + 1][0]), "+f"(o[2 * ntp + 1][1]),
                      "+f"(o[2 * ntp + 1][2]), "+f"(o[2 * ntp + 1][3])
                    : "r"(a0), "r"(a1), "r"(a2), "r"(a3), "r"(v2), "r"(v3));
            }
        }
    }

    float inv0 = 1.0f / l0, inv1 = 1.0f / l1;
    int srow0 = q0 + row_a;
    int srow1 = srow0 + 8;
    #pragma unroll
    for (int nt = 0; nt < 8; nt++) {
        int c = h * 64 + nt * 8 + 2 * q;
        *(unsigned*)(O + ((size_t)srow0 * BATCH + b) * DMODEL + c) =
            packh2(o[nt][0] * inv0, o[nt][1] * inv0);
        *(unsigned*)(O + ((size_t)srow1 * BATCH + b) * DMODEL + c) =
            packh2(o[nt][2] * inv1, o[nt][3] * inv1);
    }
}

// ---------------- host orchestration ----------------
extern "C" void kernel_launch(void* const* d_in, const int* in_sizes, int n_in,
                              void* d_out, int out_size)
{
    const float* x   = (const float*)d_in[0];
    const float* n1w = (const float*)d_in[1];
    const float* wq  = (const float*)d_in[2];
    const float* bq  = (const float*)d_in[3];
    const float* wk  = (const float*)d_in[4];
    const float* bk  = (const float*)d_in[5];
    const float* wv  = (const float*)d_in[6];
    const float* bv  = (const float*)d_in[7];
    const float* qnw = (const float*)d_in[8];
    const float* knw = (const float*)d_in[9];
    const float* wo  = (const float*)d_in[10];
    const float* bo  = (const float*)d_in[11];
    const float* n2w = (const float*)d_in[12];
    const float* w1  = (const float*)d_in[13];
    const float* b1  = (const float*)d_in[14];
    const float* w2  = (const float*)d_in[15];
    const float* b2  = (const float*)d_in[16];

    __half *ph, *pwqkv, *pqkv, *pattn, *ph2, *pmid, *pwor, *pw1r, *pw2r, *pq, *pk, *pv;
    float *pbqkv, *px1;
    float2* prope;
    cudaGetSymbolAddress((void**)&ph,    g_h);
    cudaGetSymbolAddress((void**)&pwqkv, g_wqkv);
    cudaGetSymbolAddress((void**)&pbqkv, g_bqkv);
    cudaGetSymbolAddress((void**)&pqkv,  g_qkv);
    cudaGetSymbolAddress((void**)&pq,    g_q);
    cudaGetSymbolAddress((void**)&pk,    g_k);
    cudaGetSymbolAddress((void**)&pv,    g_v);
    cudaGetSymbolAddress((void**)&pattn, g_attn);
    cudaGetSymbolAddress((void**)&px1,   g_x1);
    cudaGetSymbolAddress((void**)&ph2,   g_h2);
    cudaGetSymbolAddress((void**)&pmid,  g_mid);
    cudaGetSymbolAddress((void**)&pwor,  g_wor);
    cudaGetSymbolAddress((void**)&pw1r,  g_w1r);
    cudaGetSymbolAddress((void**)&pw2r,  g_w2r);
    cudaGetSymbolAddress((void**)&prope, g_rope);

    cudaFuncSetAttribute(gemm_f16_kernel<1>,
                         cudaFuncAttributeMaxDynamicSharedMemorySize, GF_SMEM_BYTES);
    cudaFuncSetAttribute(gemm_f16_kernel<2>,
                         cudaFuncAttributeMaxDynamicSharedMemorySize, GF_SMEM_BYTES);
    cudaFuncSetAttribute(gemm_f16_kernel<3>,
                         cudaFuncAttributeMaxDynamicSharedMemorySize, GF_SMEM_BYTES);

    prep_kernel<<<PREP_TOTAL, 256>>>(wq, wk, wv, bq, bk, bv, wo, w1, w2,
                                     pwqkv, pbqkv, pwor, pw1r, pw2r, prope);

    rmsnorm_kernel<<<NTOK, 256>>>(x, n1w, ph);
    gemm_f16_kernel<3><<<dim3(QKVN / 128, NTOK / 128), 128, GF_SMEM_BYTES>>>(
        ph, pwqkv, pbqkv, nullptr, pqkv, NTOK, QKVN, DMODEL);
    qkrope_kernel<<<dim3(NTOK, 6), dim3(64, 4)>>>(pqkv, qnw, knw, prope, pq, pk, pv);
    attn_f16_kernel<<<dim3(S_LEN / 64, BATCH * NHEAD), 128>>>(pq, pk, pv, pattn);
    gemm_f16_kernel<2><<<dim3(DMODEL / 128, NTOK / 128), 128, GF_SMEM_BYTES>>>(
        pattn, pwor, bo, x, px1, NTOK, DMODEL, DMODEL);
    rmsnorm_kernel<<<NTOK, 256>>>(px1, n2w, ph2);
    gemm_f16_kernel<1><<<dim3(DFF / 128, NTOK / 128), 128, GF_SMEM_BYTES>>>(
        ph2, pw1r, b1, nullptr, pmid, NTOK, DFF, DMODEL);
    gemm_f16_kernel<2><<<dim3(DMODEL / 128, NTOK / 128), 128, GF_SMEM_BYTES>>>(
        pmid, pw2r, b2, px1, d_out, NTOK, DMODEL, DFF);
}

// round 16
// speedup vs baseline: 1.0576x; 1.0105x over previous
#include <cuda_runtime.h>
#include <cuda_fp16.h>
#include <math.h>
#include <stdint.h>

#define S_LEN   2048
#define BATCH   2
#define DMODEL  1024
#define NHEAD   16
#define NKV     4
#define HEADDIM 64
#define NTOK    4096            // S_LEN * BATCH
#define DFF     4096            // 4 * DMODEL
#define QKVN    1536            // 1024 + 256 + 256
#define EPS_F   1e-5f
#define QK_SCALE 0.03125f       // D^-0.5 = 1/32

// fp16 GEMM smem: 4 stages, tiles [128 rows][40 halfs] (stride 80B)
#define GF_TILE_BYTES 10240     // 128*80
#define GF_STAGES 4
#define GF_SMEM_BYTES (2 * GF_STAGES * GF_TILE_BYTES)   // 81920

// fused prep grid ranges (32x32 tiles) + rope table
#define PREP_QKV_BLKS   (48 * 32)          // 1536
#define PREP_WO_BLKS    (32 * 32)          // 1024
#define PREP_W1_BLKS    (128 * 32)         // 4096
#define PREP_W2_BLKS    (32 * 128)         // 4096
#define PREP_ROPE_BLKS  (S_LEN * 32 / 256) // 256
#define PREP_TOTAL (PREP_QKV_BLKS + PREP_WO_BLKS + PREP_W1_BLKS + PREP_W2_BLKS + PREP_ROPE_BLKS)

// ---------------- scratch (__device__ globals; no allocation allowed) ----------------
__device__ __half g_h   [NTOK * DMODEL];
__device__ __half g_wqkv[QKVN * DMODEL];      // transposed [N,K]
__device__ float  g_bqkv[QKVN];
__device__ __half g_qkv [NTOK * QKVN];
__device__ __half g_q   [BATCH * NHEAD * S_LEN * HEADDIM];
__device__ __half g_k   [BATCH * NKV   * S_LEN * HEADDIM];
__device__ __half g_v   [BATCH * NKV   * S_LEN * HEADDIM];
__device__ __half g_attn[NTOK * DMODEL];
__device__ float  g_x1  [NTOK * DMODEL];
__device__ __half g_h2  [NTOK * DMODEL];
__device__ __half g_mid [NTOK * DFF];
__device__ __half g_wor [DMODEL * DMODEL];    // transposed
__device__ __half g_w1r [DFF * DMODEL];       // transposed
__device__ __half g_w2r [DMODEL * DFF];       // transposed
__device__ float2 g_rope[S_LEN * 32];         // (cos, sin) per (s, j)

__device__ __forceinline__ void cp16s(uint32_t daddr, const void* src) {
    asm volatile("cp.async.ca.shared.global [%0], [%1], 16;" :: "r"(daddr), "l"(src));
}
__device__ __forceinline__ unsigned packh2(float a, float b) {
    __half2 h = __floats2half2_rn(a, b);
    return *(unsigned*)&h;
}

// ---------------- fused weight prep + rope table, one launch --------
__device__ __forceinline__ void tile_transpose(const float* __restrict__ src,
                                               __half* __restrict__ dst,
                                               int R, int C, int bx, int by, int tx, int ty)
{
    __shared__ float t[32][33];
    #pragma unroll
    for (int j = 0; j < 4; j++)
        t[ty + 8 * j][tx] = src[(size_t)(by + ty + 8 * j) * C + bx + tx];
    __syncthreads();
    #pragma unroll
    for (int j = 0; j < 4; j++)
        dst[(size_t)(bx + ty + 8 * j) * R + by + tx] = __float2half_rn(t[tx][ty + 8 * j]);
}

__global__ __launch_bounds__(256)
void prep_kernel(const float* __restrict__ wq, const float* __restrict__ wk,
                 const float* __restrict__ wv, const float* __restrict__ bq,
                 const float* __restrict__ bk, const float* __restrict__ bv,
                 const float* __restrict__ wo, const float* __restrict__ w1,
                 const float* __restrict__ w2,
                 __half* __restrict__ Wqkv, float* __restrict__ bias,
                 __half* __restrict__ Wor, __half* __restrict__ W1r,
                 __half* __restrict__ W2r, float2* __restrict__ rope)
{
    int blk = blockIdx.x;
    int tx = threadIdx.x & 31;
    int ty = threadIdx.x >> 5;

    if (blk < PREP_QKV_BLKS) {
        __shared__ float t[32][33];
        int bx = (blk % 48) * 32;   // c base
        int by = (blk / 48) * 32;   // k base
        #pragma unroll
        for (int j = 0; j < 4; j++) {
            int k = by + ty + 8 * j;
            int c = bx + tx;
            float v;
            if (c < 1024)       v = wq[(size_t)k * 1024 + c];
            else if (c < 1280)  v = wk[(size_t)k * 256 + (c - 1024)];
            else                v = wv[(size_t)k * 256 + (c - 1280)];
            t[ty + 8 * j][tx] = v;
        }
        __syncthreads();
        #pragma unroll
        for (int j = 0; j < 4; j++) {
            int c = bx + ty + 8 * j;
            Wqkv[(size_t)c * DMODEL + by + tx] = __float2half_rn(t[tx][ty + 8 * j]);
        }
        if (blk < 6) {
            int i = blk * 256 + threadIdx.x;
            if (i < QKVN)
                bias[i] = (i < 1024) ? bq[i] : (i < 1280 ? bk[i - 1024] : bv[i - 1280]);
        }
        return;
    }
    blk -= PREP_QKV_BLKS;
    if (blk < PREP_WO_BLKS) {
        tile_transpose(wo, Wor, DMODEL, DMODEL, (blk % 32) * 32, (blk / 32) * 32, tx, ty);
        return;
    }
    blk -= PREP_WO_BLKS;
    if (blk < PREP_W1_BLKS) {
        tile_transpose(w1, W1r, DMODEL, DFF, (blk % 128) * 32, (blk / 128) * 32, tx, ty);
        return;
    }
    blk -= PREP_W1_BLKS;
    if (blk < PREP_W2_BLKS) {
        tile_transpose(w2, W2r, DFF, DMODEL, (blk % 32) * 32, (blk / 32) * 32, tx, ty);
        return;
    }
    blk -= PREP_W2_BLKS;
    int idx = blk * 256 + threadIdx.x;
    int s = idx >> 5, j = idx & 31;
    float invf = exp2f(-(float)j * (13.287712379549449f / 32.0f));
    float ang = (float)s * invf;
    float sn, cs;
    sincosf(ang, &sn, &cs);
    rope[idx] = make_float2(cs, sn);
}

// ---------------- RMSNorm over D=1024, fp16 output ----------------
__global__ __launch_bounds__(256)
void rmsnorm_kernel(const float* __restrict__ x, const float* __restrict__ w,
                    __half* __restrict__ y)
{
    int row = blockIdx.x;
    int i = threadIdx.x;
    const float* xr = x + (size_t)row * DMODEL;
    float4 xv = *(const float4*)(xr + i * 4);
    float ss = xv.x * xv.x + xv.y * xv.y + xv.z * xv.z + xv.w * xv.w;
    #pragma unroll
    for (int off = 16; off; off >>= 1) ss += __shfl_xor_sync(0xffffffffu, ss, off);
    __shared__ float red[8];
    __shared__ float s_sc;
    if ((i & 31) == 0) red[i >> 5] = ss;
    __syncthreads();
    if (i == 0) {
        float tot = 0.f;
        #pragma unroll
        for (int kk = 0; kk < 8; kk++) tot += red[kk];
        s_sc = rsqrtf(tot * (1.0f / DMODEL) + EPS_F);
    }
    __syncthreads();
    float sc = s_sc;
    float4 wv = *(const float4*)(w + i * 4);
    uint2 u;
    u.x = packh2(xv.x * sc * wv.x, xv.y * sc * wv.y);
    u.y = packh2(xv.z * sc * wv.z, xv.w * sc * wv.w);
    *(uint2*)(y + (size_t)row * DMODEL + i * 4) = u;
}

// ---------------- per-head QK RMSNorm + RoPE (table) + relayout ----------------
__global__ __launch_bounds__(256)
void qkrope_kernel(const __half* __restrict__ qkv, const float* __restrict__ qn_w,
                   const float* __restrict__ kn_w, const float2* __restrict__ rope,
                   __half* __restrict__ Qo, __half* __restrict__ Ko,
                   __half* __restrict__ Vo)
{
    int t = blockIdx.x;            // token = s*BATCH + b
    int ty = threadIdx.y;          // 0..3
    int slot = blockIdx.y * 4 + ty;
    int i = threadIdx.x;           // 0..63
    int s = t / BATCH, b = t % BATCH;
    __shared__ float buf[4][64];
    __shared__ float red[4][2];

    if (slot >= 20) {   // V: pure relayout (whole block is V)
        int vh = slot - 20;
        Vo[((size_t)(b * NKV + vh) * S_LEN + s) * 64 + i] =
            qkv[(size_t)t * QKVN + 1280 + vh * 64 + i];
        return;
    }

    bool is_q = (slot < 16);
    int col = is_q ? (slot * 64 + i) : (1024 + (slot - 16) * 64 + i);
    float v = __half2float(qkv[(size_t)t * QKVN + col]);
    float ss = v * v;
    #pragma unroll
    for (int off = 16; off; off >>= 1) ss += __shfl_xor_sync(0xffffffffu, ss, off);
    if ((i & 31) == 0) red[ty][i >> 5] = ss;
    __syncthreads();
    float tot = red[ty][0] + red[ty][1];
    float sc = rsqrtf(tot * (1.0f / 64.0f) + EPS_F);
    const float* w = is_q ? qn_w : kn_w;
    float nv = v * sc * w[i];
    buf[ty][i] = nv;
    __syncthreads();
    float rot = (i < 32) ? -buf[ty][i + 32] : buf[ty][i - 32];
    float2 cs2 = rope[(size_t)s * 32 + (i & 31)];
    float outv = nv * cs2.x + rot * cs2.y;
    if (is_q) {
        outv *= QK_SCALE;
        Qo[((size_t)(b * NHEAD + slot) * S_LEN + s) * 64 + i] = __float2half_rn(outv);
    } else {
        Ko[((size_t)(b * NKV + (slot - 16)) * S_LEN + s) * 64 + i] = __float2half_rn(outv);
    }
}

// ---------------- fp16 GEMM stage loader: 8 cp.async per thread ----------------
__device__ __forceinline__ void gf_load(uint32_t sA, uint32_t sB,
                                        const __half* Ag, const __half* Bg,
                                        int K, int k0, int tid)
{
    int r0 = tid >> 2;             // 0..31
    int ch = (tid & 3) << 3;       // half offset in row: 0,8,16,24
    #pragma unroll
    for (int j = 0; j < 4; j++) {
        int r = r0 + 32 * j;
        uint32_t so = (uint32_t)(r * 80 + ch * 2);
        cp16s(sA + so, Ag + (size_t)r * K + k0 + ch);
        cp16s(sB + so, Bg + (size_t)r * K + k0 + ch);
    }
    asm volatile("cp.async.commit_group;" ::: "memory");
}

// ---------------- fp16 GEMM ----------------
// EPI: 1 = gelu(+bias) fp16 out, 2 = +bias+residual fp32 out, 3 = +bias fp16 out
template<int EPI>
__global__ __launch_bounds__(128)
void gemm_f16_kernel(const __half* __restrict__ A, const __half* __restrict__ Bt,
                     const float* __restrict__ bias, const float* __restrict__ res,
                     void* __restrict__ Cout, int M, int N, int K)
{
    extern __shared__ char smc[];
    uint32_t smem_base;
    asm("{ .reg .u64 t; cvta.to.shared.u64 t, %1; cvt.u32.u64 %0, t; }"
        : "=r"(smem_base) : "l"(smc));

    int tid  = threadIdx.x;
    int wid  = tid >> 5, lane = tid & 31;
    int g    = lane >> 2;
    int q    = lane & 3;
    int wm   = (wid >> 1) * 64;
    int wn   = (wid & 1) * 64;

    int row0 = blockIdx.y * 128;
    int col0 = blockIdx.x * 128;
    const __half* Ag = A  + (size_t)row0 * K;
    const __half* Bg = Bt + (size_t)col0 * K;

    float acc[4][8][4];
    #pragma unroll
    for (int mt = 0; mt < 4; mt++)
        #pragma unroll
        for (int nt = 0; nt < 8; nt++)
            #pragma unroll
            for (int r = 0; r < 4; r++) acc[mt][nt][r] = 0.f;

    const int KT = K >> 5;

    #pragma unroll
    for (int st = 0; st < 3; st++)
        gf_load(smem_base + st * GF_TILE_BYTES,
                smem_base + (GF_STAGES + st) * GF_TILE_BYTES,
                Ag, Bg, K, st * 32, tid);

    for (int kt = 0; kt < KT; kt++) {
        asm volatile("cp.async.wait_group 2;" ::: "memory");
        __syncthreads();

        if (kt + 3 < KT) {
            int st = (kt + 3) & 3;
            gf_load(smem_base + st * GF_TILE_BYTES,
                    smem_base + (GF_STAGES + st) * GF_TILE_BYTES,
                    Ag, Bg, K, (kt + 3) * 32, tid);
        }

        int st = kt & 3;
        const __half* As = (const __half*)(smc + st * GF_TILE_BYTES);
        const __half* Bs = (const __half*)(smc + (GF_STAGES + st) * GF_TILE_BYTES);

        #pragma unroll
        for (int kk = 0; kk < 32; kk += 16) {
            unsigned af[4][4];
            #pragma unroll
            for (int mt = 0; mt < 4; mt++) {
                int r = wm + mt * 16 + g;
                af[mt][0] = *(const unsigned*)(As + r * 40 + kk + 2 * q);
                af[mt][1] = *(const unsigned*)(As + (r + 8) * 40 + kk + 2 * q);
                af[mt][2] = *(const unsigned*)(As + r * 40 + kk + 2 * q + 8);
                af[mt][3] = *(const unsigned*)(As + (r + 8) * 40 + kk + 2 * q + 8);
            }
            unsigned bf[8][2];
            #pragma unroll
            for (int nt = 0; nt < 8; nt++) {
                int c = wn + nt * 8 + g;
                bf[nt][0] = *(const unsigned*)(Bs + c * 40 + kk + 2 * q);
                bf[nt][1] = *(const unsigned*)(Bs + c * 40 + kk + 2 * q + 8);
            }
            #pragma unroll
            for (int mt = 0; mt < 4; mt++)
                #pragma unroll
                for (int nt = 0; nt < 8; nt++) {
                    asm volatile(
                        "mma.sync.aligned.m16n8k16.row.col.f32.f16.f16.f32 "
                        "{%0,%1,%2,%3}, {%4,%5,%6,%7}, {%8,%9}, {%0,%1,%2,%3};"
                        : "+f"(acc[mt][nt][0]), "+f"(acc[mt][nt][1]),
                          "+f"(acc[mt][nt][2]), "+f"(acc[mt][nt][3])
                        : "r"(af[mt][0]), "r"(af[mt][1]), "r"(af[mt][2]), "r"(af[mt][3]),
                          "r"(bf[nt][0]), "r"(bf[nt][1]));
                }
        }
    }

    #pragma unroll
    for (int mt = 0; mt < 4; mt++) {
        int r = row0 + wm + mt * 16 + g;
        #pragma unroll
        for (int nt = 0; nt < 8; nt++) {
            int c = col0 + wn + nt * 8 + 2 * q;
            float bv0 = bias[c], bv1 = bias[c + 1];
            float v00 = acc[mt][nt][0] + bv0;
            float v01 = acc[mt][nt][1] + bv1;
            float v10 = acc[mt][nt][2] + bv0;
            float v11 = acc[mt][nt][3] + bv1;
            if (EPI == 1) {
                v00 = 0.5f * v00 * (1.0f + erff(v00 * 0.70710678118654752f));
                v01 = 0.5f * v01 * (1.0f + erff(v01 * 0.70710678118654752f));
                v10 = 0.5f * v10 * (1.0f + erff(v10 * 0.70710678118654752f));
                v11 = 0.5f * v11 * (1.0f + erff(v11 * 0.70710678118654752f));
            }
            if (EPI == 1 || EPI == 3) {
                __half* C = (__half*)Cout;
                *(unsigned*)(C + (size_t)r * N + c)       = packh2(v00, v01);
                *(unsigned*)(C + (size_t)(r + 8) * N + c) = packh2(v10, v11);
            } else {
                float* C = (float*)Cout;
                if (EPI == 2) {
                    float2 r0 = *(const float2*)(res + (size_t)r * N + c);
                    float2 r1 = *(const float2*)(res + (size_t)(r + 8) * N + c);
                    v00 += r0.x; v01 += r0.y;
                    v10 += r1.x; v11 += r1.y;
                }
                *(float2*)(C + (size_t)r * N + c)       = make_float2(v00, v01);
                *(float2*)(C + (size_t)(r + 8) * N + c) = make_float2(v10, v11);
            }
        }
    }
}

// ---------------- fp16 flash attention: BQ=128, 8 warps, single-buffer K/V -----------
// Warp w owns q-rows 16w..16w+15 within the 128-row tile. Fully-masked kv tiles are
// skipped per-warp (no barrier inside compute). LJF scheduling; single resident wave.
__global__ __launch_bounds__(256)
void attn_f16_kernel(const __half* __restrict__ Q, const __half* __restrict__ K,
                     const __half* __restrict__ V, __half* __restrict__ O)
{
    __shared__ __half Qs[128][72];
    __shared__ __half Ks[64][72];
    __shared__ __half Vs[64][72];

    int tid  = threadIdx.x;
    int wid  = tid >> 5, lane = tid & 31;
    int g    = lane >> 2;
    int q    = lane & 3;
    int qt   = gridDim.x - 1 - blockIdx.x;   // longest-job-first
    int bh   = blockIdx.y;
    int b    = bh >> 4;
    int h    = bh & 15;
    int kvh  = h >> 2;
    int q0   = qt * 128;

    const __half* Qb = Q + (size_t)(b * NHEAD + h)  * S_LEN * 64 + (size_t)q0 * 64;
    const __half* Kb = K + (size_t)(b * NKV  + kvh) * S_LEN * 64;
    const __half* Vb = V + (size_t)(b * NKV  + kvh) * S_LEN * 64;

    // stage Q: 128 rows x 64 halves
    for (int i = tid; i < 128 * 8; i += 256) {
        int r = i >> 3, c = (i & 7) * 8;
        *(uint4*)&Qs[r][c] = *(const uint4*)(Qb + (size_t)r * 64 + c);
    }
    __syncthreads();

    int row_a = 16 * wid + g;      // 0..127
    int grow = q0 + row_a;         // global q row (lower of the pair)
    unsigned qa[4][4];
    #pragma unroll
    for (int c4 = 0; c4 < 4; c4++) {
        int kk = c4 * 16;
        qa[c4][0] = *(const unsigned*)&Qs[row_a][kk + 2 * q];
        qa[c4][1] = *(const unsigned*)&Qs[row_a + 8][kk + 2 * q];
        qa[c4][2] = *(const unsigned*)&Qs[row_a][kk + 2 * q + 8];
        qa[c4][3] = *(const unsigned*)&Qs[row_a + 8][kk + 2 * q + 8];
    }

    float m0 = -INFINITY, m1 = -INFINITY, l0 = 0.f, l1 = 0.f;
    float o[8][4];
    #pragma unroll
    for (int nt = 0; nt < 8; nt++)
        #pragma unroll
        for (int r = 0; r < 4; r++) o[nt][r] = 0.f;

    int nkt = 2 * qt + 2;          // kv tiles of 64 covering [0, q0+128)
    int vmat = lane >> 3;
    int vrow = lane & 7;

    for (int jt = 0; jt < nkt; ++jt) {
        int j0 = jt * 64;
        __syncthreads();
        for (int i = tid; i < 64 * 8; i += 256) {
            int r = i >> 3, c = (i & 7) * 8;
            *(uint4*)&Ks[r][c] = *(const uint4*)(Kb + (size_t)(j0 + r) * 64 + c);
            *(uint4*)&Vs[r][c] = *(const uint4*)(Vb + (size_t)(j0 + r) * 64 + c);
        }
        __syncthreads();

        // warp-uniform skip: tile entirely in the future for this warp's rows
        if (j0 > grow + 8) continue;

        float s[8][4];
        #pragma unroll
        for (int nt = 0; nt < 8; nt++)
            #pragma unroll
            for (int r = 0; r < 4; r++) s[nt][r] = 0.f;

        #pragma unroll
        for (int c4 = 0; c4 < 4; c4++) {
            int kk = c4 * 16;
            #pragma unroll
            for (int nt = 0; nt < 8; nt++) {
                unsigned b0 = *(const unsigned*)&Ks[nt * 8 + g][kk + 2 * q];
                unsigned b1 = *(const unsigned*)&Ks[nt * 8 + g][kk + 2 * q + 8];
                asm volatile(
                    "mma.sync.aligned.m16n8k16.row.col.f32.f16.f16.f32 "
                    "{%0,%1,%2,%3}, {%4,%5,%6,%7}, {%8,%9}, {%0,%1,%2,%3};"
                    : "+f"(s[nt][0]), "+f"(s[nt][1]), "+f"(s[nt][2]), "+f"(s[nt][3])
                    : "r"(qa[c4][0]), "r"(qa[c4][1]), "r"(qa[c4][2]), "r"(qa[c4][3]),
                      "r"(b0), "r"(b1));
            }
        }

        // causal mask for tiles crossing this warp's diagonal
        if (j0 + 63 > grow) {
            #pragma unroll
            for (int nt = 0; nt < 8; nt++) {
                int colg = j0 + nt * 8 + 2 * q;
                if (colg     > grow)     s[nt][0] = -INFINITY;
                if (colg + 1 > grow)     s[nt][1] = -INFINITY;
                if (colg     > grow + 8) s[nt][2] = -INFINITY;
                if (colg + 1 > grow + 8) s[nt][3] = -INFINITY;
            }
        }

        float mt0 = -INFINITY, mt1 = -INFINITY;
        #pragma unroll
        for (int nt = 0; nt < 8; nt++) {
            mt0 = fmaxf(mt0, fmaxf(s[nt][0], s[nt][1]));
            mt1 = fmaxf(mt1, fmaxf(s[nt][2], s[nt][3]));
        }
        #pragma unroll
        for (int off = 1; off < 4; off <<= 1) {
            mt0 = fmaxf(mt0, __shfl_xor_sync(0xffffffffu, mt0, off));
            mt1 = fmaxf(mt1, __shfl_xor_sync(0xffffffffu, mt1, off));
        }
        float mn0 = fmaxf(m0, mt0), mn1 = fmaxf(m1, mt1);
        float al0 = __expf(m0 - mn0), al1 = __expf(m1 - mn1);
        m0 = mn0; m1 = mn1;
        float ps0 = 0.f, ps1 = 0.f;
        #pragma unroll
        for (int nt = 0; nt < 8; nt++) {
            s[nt][0] = __expf(s[nt][0] - mn0);
            s[nt][1] = __expf(s[nt][1] - mn0);
            s[nt][2] = __expf(s[nt][2] - mn1);
            s[nt][3] = __expf(s[nt][3] - mn1);
            ps0 += s[nt][0] + s[nt][1];
            ps1 += s[nt][2] + s[nt][3];
            o[nt][0] *= al0; o[nt][1] *= al0;
            o[nt][2] *= al1; o[nt][3] *= al1;
        }
        #pragma unroll
        for (int off = 1; off < 4; off <<= 1) {
            ps0 += __shfl_xor_sync(0xffffffffu, ps0, off);
            ps1 += __shfl_xor_sync(0xffffffffu, ps1, off);
        }
        l0 = l0 * al0 + ps0;
        l1 = l1 * al1 + ps1;

        #pragma unroll
        for (int kc = 0; kc < 4; kc++) {
            unsigned a0 = packh2(s[2 * kc][0],     s[2 * kc][1]);
            unsigned a1 = packh2(s[2 * kc][2],     s[2 * kc][3]);
            unsigned a2 = packh2(s[2 * kc + 1][0], s[2 * kc + 1][1]);
            unsigned a3 = packh2(s[2 * kc + 1][2], s[2 * kc + 1][3]);
            #pragma unroll
            for (int ntp = 0; ntp < 4; ntp++) {
                const __half* vp = &Vs[kc * 16 + (vmat & 1) * 8 + vrow]
                                      [ntp * 16 + (vmat >> 1) * 8];
                uint32_t vaddr = (uint32_t)__cvta_generic_to_shared(vp);
                unsigned v0, v1, v2, v3;
                asm volatile(
                    "ldmatrix.sync.aligned.m8n8.x4.trans.shared.b16 {%0,%1,%2,%3}, [%4];"
                    : "=r"(v0), "=r"(v1), "=r"(v2), "=r"(v3) : "r"(vaddr));
                asm volatile(
                    "mma.sync.aligned.m16n8k16.row.col.f32.f16.f16.f32 "
                    "{%0,%1,%2,%3}, {%4,%5,%6,%7}, {%8,%9}, {%0,%1,%2,%3};"
                    : "+f"(o[2 * ntp][0]), "+f"(o[2 * ntp][1]),
                      "+f"(o[2 * ntp][2]), "+f"(o[2 * ntp][3])
                    : "r"(a0), "r"(a1), "r"(a2), "r"(a3), "r"(v0), "r"(v1));
                asm volatile(
                    "mma.sync.aligned.m16n8k16.row.col.f32.f16.f16.f32 "
                    "{%0,%1,%2,%3}, {%4,%5,%6,%7}, {%8,%9}, {%0,%1,%2,%3};"
                    : "+f"(o[2 * ntp + 1][0]), "+f"(o[2 * ntp + 1][1]),
                      "+f"(o[2 * ntp + 1][2]), "+f"(o[2 * ntp + 1][3])
                    : "r"(a0), "r"(a1), "r"(a2), "r"(a3), "r"(v2), "r"(v3));
            }
        }
    }

    float inv0 = 1.0f / l0, inv1 = 1.0f / l1;
    int srow0 = q0 + row_a;
    int srow1 = srow0 + 8;
    #pragma unroll
    for (int nt = 0; nt < 8; nt++) {
        int c = h * 64 + nt * 8 + 2 * q;
        *(unsigned*)(O + ((size_t)srow0 * BATCH + b) * DMODEL + c) =
            packh2(o[nt][0] * inv0, o[nt][1] * inv0);
        *(unsigned*)(O + ((size_t)srow1 * BATCH + b) * DMODEL + c) =
            packh2(o[nt][2] * inv1, o[nt][3] * inv1);
    }
}

// ---------------- host orchestration ----------------
extern "C" void kernel_launch(void* const* d_in, const int* in_sizes, int n_in,
                              void* d_out, int out_size)
{
    const float* x   = (const float*)d_in[0];
    const float* n1w = (const float*)d_in[1];
    const float* wq  = (const float*)d_in[2];
    const float* bq  = (const float*)d_in[3];
    const float* wk  = (const float*)d_in[4];
    const float* bk  = (const float*)d_in[5];
    const float* wv  = (const float*)d_in[6];
    const float* bv  = (const float*)d_in[7];
    const float* qnw = (const float*)d_in[8];
    const float* knw = (const float*)d_in[9];
    const float* wo  = (const float*)d_in[10];
    const float* bo  = (const float*)d_in[11];
    const float* n2w = (const float*)d_in[12];
    const float* w1  = (const float*)d_in[13];
    const float* b1  = (const float*)d_in[14];
    const float* w2  = (const float*)d_in[15];
    const float* b2  = (const float*)d_in[16];

    __half *ph, *pwqkv, *pqkv, *pattn, *ph2, *pmid, *pwor, *pw1r, *pw2r, *pq, *pk, *pv;
    float *pbqkv, *px1;
    float2* prope;
    cudaGetSymbolAddress((void**)&ph,    g_h);
    cudaGetSymbolAddress((void**)&pwqkv, g_wqkv);
    cudaGetSymbolAddress((void**)&pbqkv, g_bqkv);
    cudaGetSymbolAddress((void**)&pqkv,  g_qkv);
    cudaGetSymbolAddress((void**)&pq,    g_q);
    cudaGetSymbolAddress((void**)&pk,    g_k);
    cudaGetSymbolAddress((void**)&pv,    g_v);
    cudaGetSymbolAddress((void**)&pattn, g_attn);
    cudaGetSymbolAddress((void**)&px1,   g_x1);
    cudaGetSymbolAddress((void**)&ph2,   g_h2);
    cudaGetSymbolAddress((void**)&pmid,  g_mid);
    cudaGetSymbolAddress((void**)&pwor,  g_wor);
    cudaGetSymbolAddress((void**)&pw1r,  g_w1r);
    cudaGetSymbolAddress((void**)&pw2r,  g_w2r);
    cudaGetSymbolAddress((void**)&prope, g_rope);

    cudaFuncSetAttribute(gemm_f16_kernel<1>,
                         cudaFuncAttributeMaxDynamicSharedMemorySize, GF_SMEM_BYTES);
    cudaFuncSetAttribute(gemm_f16_kernel<2>,
                         cudaFuncAttributeMaxDynamicSharedMemorySize, GF_SMEM_BYTES);
    cudaFuncSetAttribute(gemm_f16_kernel<3>,
                         cudaFuncAttributeMaxDynamicSharedMemorySize, GF_SMEM_BYTES);

    prep_kernel<<<PREP_TOTAL, 256>>>(wq, wk, wv, bq, bk, bv, wo, w1, w2,
                                     pwqkv, pbqkv, pwor, pw1r, pw2r, prope);

    rmsnorm_kernel<<<NTOK, 256>>>(x, n1w, ph);
    gemm_f16_kernel<3><<<dim3(QKVN / 128, NTOK / 128), 128, GF_SMEM_BYTES>>>(
        ph, pwqkv, pbqkv, nullptr, pqkv, NTOK, QKVN, DMODEL);
    qkrope_kernel<<<dim3(NTOK, 6), dim3(64, 4)>>>(pqkv, qnw, knw, prope, pq, pk, pv);
    attn_f16_kernel<<<dim3(S_LEN / 128, BATCH * NHEAD), 256>>>(pq, pk, pv, pattn);
    gemm_f16_kernel<2><<<dim3(DMODEL / 128, NTOK / 128), 128, GF_SMEM_BYTES>>>(
        pattn, pwor, bo, x, px1, NTOK, DMODEL, DMODEL);
    rmsnorm_kernel<<<NTOK, 256>>>(px1, n2w, ph2);
    gemm_f16_kernel<1><<<dim3(DFF / 128, NTOK / 128), 128, GF_SMEM_BYTES>>>(
        ph2, pw1r, b1, nullptr, pmid, NTOK, DFF, DMODEL);
    gemm_f16_kernel<2><<<dim3(DMODEL / 128, NTOK / 128), 128, GF_SMEM_BYTES>>>(
        pmid, pw2r, b2, px1, d_out, NTOK, DMODEL, DFF);
}

// round 17
// speedup vs baseline: 1.0797x; 1.0210x over previous
#include <cuda_runtime.h>
#include <cuda_fp16.h>
#include <math.h>
#include <stdint.h>

#define S_LEN   2048
#define BATCH   2
#define DMODEL  1024
#define NHEAD   16
#define NKV     4
#define HEADDIM 64
#define NTOK    4096            // S_LEN * BATCH
#define DFF     4096            // 4 * DMODEL
#define QKVN    1536            // 1024 + 256 + 256
#define EPS_F   1e-5f
#define QK_SCALE 0.03125f       // D^-0.5 = 1/32

// fp16 GEMM smem: 4 stages, tiles [128 rows][40 halfs] (stride 80B)
#define GF_TILE_BYTES 10240     // 128*80
#define GF_STAGES 4
#define GF_SMEM_BYTES (2 * GF_STAGES * GF_TILE_BYTES)   // 81920

// fused prep grid ranges (32x32 tiles) + rope table
#define PREP_QKV_BLKS   (48 * 32)          // 1536
#define PREP_WO_BLKS    (32 * 32)          // 1024
#define PREP_W1_BLKS    (128 * 32)         // 4096
#define PREP_W2_BLKS    (32 * 128)         // 4096
#define PREP_ROPE_BLKS  (S_LEN * 32 / 256) // 256
#define PREP_TOTAL (PREP_QKV_BLKS + PREP_WO_BLKS + PREP_W1_BLKS + PREP_W2_BLKS + PREP_ROPE_BLKS)

// ---------------- scratch (__device__ globals; no allocation allowed) ----------------
__device__ __half g_h   [NTOK * DMODEL];
__device__ __half g_wqkv[QKVN * DMODEL];      // transposed [N,K]
__device__ float  g_bqkv[QKVN];
__device__ __half g_qkv [NTOK * QKVN];
__device__ __half g_q   [BATCH * NHEAD * S_LEN * HEADDIM];
__device__ __half g_k   [BATCH * NKV   * S_LEN * HEADDIM];
__device__ __half g_v   [BATCH * NKV   * S_LEN * HEADDIM];
__device__ __half g_attn[NTOK * DMODEL];
__device__ float  g_x1  [NTOK * DMODEL];
__device__ __half g_h2  [NTOK * DMODEL];
__device__ __half g_mid [NTOK * DFF];
__device__ __half g_wor [DMODEL * DMODEL];    // transposed
__device__ __half g_w1r [DFF * DMODEL];       // transposed
__device__ __half g_w2r [DMODEL * DFF];       // transposed
__device__ float2 g_rope[S_LEN * 32];         // (cos, sin) per (s, j)

__device__ __forceinline__ void cp16s(uint32_t daddr, const void* src) {
    asm volatile("cp.async.ca.shared.global [%0], [%1], 16;" :: "r"(daddr), "l"(src));
}
__device__ __forceinline__ unsigned packh2(float a, float b) {
    __half2 h = __floats2half2_rn(a, b);
    return *(unsigned*)&h;
}

// ---------------- fused weight prep + rope table, one launch --------
__device__ __forceinline__ void tile_transpose(const float* __restrict__ src,
                                               __half* __restrict__ dst,
                                               int R, int C, int bx, int by, int tx, int ty)
{
    __shared__ float t[32][33];
    #pragma unroll
    for (int j = 0; j < 4; j++)
        t[ty + 8 * j][tx] = src[(size_t)(by + ty + 8 * j) * C + bx + tx];
    __syncthreads();
    #pragma unroll
    for (int j = 0; j < 4; j++)
        dst[(size_t)(bx + ty + 8 * j) * R + by + tx] = __float2half_rn(t[tx][ty + 8 * j]);
}

__global__ __launch_bounds__(256)
void prep_kernel(const float* __restrict__ wq, const float* __restrict__ wk,
                 const float* __restrict__ wv, const float* __restrict__ bq,
                 const float* __restrict__ bk, const float* __restrict__ bv,
                 const float* __restrict__ wo, const float* __restrict__ w1,
                 const float* __restrict__ w2,
                 __half* __restrict__ Wqkv, float* __restrict__ bias,
                 __half* __restrict__ Wor, __half* __restrict__ W1r,
                 __half* __restrict__ W2r, float2* __restrict__ rope)
{
    int blk = blockIdx.x;
    int tx = threadIdx.x & 31;
    int ty = threadIdx.x >> 5;

    if (blk < PREP_QKV_BLKS) {
        __shared__ float t[32][33];
        int bx = (blk % 48) * 32;   // c base
        int by = (blk / 48) * 32;   // k base
        #pragma unroll
        for (int j = 0; j < 4; j++) {
            int k = by + ty + 8 * j;
            int c = bx + tx;
            float v;
            if (c < 1024)       v = wq[(size_t)k * 1024 + c];
            else if (c < 1280)  v = wk[(size_t)k * 256 + (c - 1024)];
            else                v = wv[(size_t)k * 256 + (c - 1280)];
            t[ty + 8 * j][tx] = v;
        }
        __syncthreads();
        #pragma unroll
        for (int j = 0; j < 4; j++) {
            int c = bx + ty + 8 * j;
            Wqkv[(size_t)c * DMODEL + by + tx] = __float2half_rn(t[tx][ty + 8 * j]);
        }
        if (blk < 6) {
            int i = blk * 256 + threadIdx.x;
            if (i < QKVN)
                bias[i] = (i < 1024) ? bq[i] : (i < 1280 ? bk[i - 1024] : bv[i - 1280]);
        }
        return;
    }
    blk -= PREP_QKV_BLKS;
    if (blk < PREP_WO_BLKS) {
        tile_transpose(wo, Wor, DMODEL, DMODEL, (blk % 32) * 32, (blk / 32) * 32, tx, ty);
        return;
    }
    blk -= PREP_WO_BLKS;
    if (blk < PREP_W1_BLKS) {
        tile_transpose(w1, W1r, DMODEL, DFF, (blk % 128) * 32, (blk / 128) * 32, tx, ty);
        return;
    }
    blk -= PREP_W1_BLKS;
    if (blk < PREP_W2_BLKS) {
        tile_transpose(w2, W2r, DFF, DMODEL, (blk % 32) * 32, (blk / 32) * 32, tx, ty);
        return;
    }
    blk -= PREP_W2_BLKS;
    int idx = blk * 256 + threadIdx.x;
    int s = idx >> 5, j = idx & 31;
    float invf = exp2f(-(float)j * (13.287712379549449f / 32.0f));
    float ang = (float)s * invf;
    float sn, cs;
    sincosf(ang, &sn, &cs);
    rope[idx] = make_float2(cs, sn);
}

// ---------------- RMSNorm, warp-per-row (no barriers, no smem) ----------------
__global__ __launch_bounds__(256)
void rmsnorm_kernel(const float* __restrict__ x, const float* __restrict__ w,
                    __half* __restrict__ y)
{
    int row  = blockIdx.x * 8 + (threadIdx.x >> 5);
    int lane = threadIdx.x & 31;
    const float* xr = x + (size_t)row * DMODEL;
    float4 xv[8];
    float ss = 0.f;
    #pragma unroll
    for (int j = 0; j < 8; j++) {
        xv[j] = *(const float4*)(xr + (j * 32 + lane) * 4);
        ss += xv[j].x * xv[j].x + xv[j].y * xv[j].y
            + xv[j].z * xv[j].z + xv[j].w * xv[j].w;
    }
    #pragma unroll
    for (int off = 16; off; off >>= 1) ss += __shfl_xor_sync(0xffffffffu, ss, off);
    float sc = rsqrtf(ss * (1.0f / DMODEL) + EPS_F);
    #pragma unroll
    for (int j = 0; j < 8; j++) {
        float4 wv = *(const float4*)(w + (j * 32 + lane) * 4);
        uint2 u;
        u.x = packh2(xv[j].x * sc * wv.x, xv[j].y * sc * wv.y);
        u.y = packh2(xv[j].z * sc * wv.z, xv[j].w * sc * wv.w);
        *(uint2*)(y + (size_t)row * DMODEL + (j * 32 + lane) * 4) = u;
    }
}

// ---------------- qkrope, warp-per-slot (no barriers, no smem) ----------------
// grid (NTOK, 3), block 256 = 8 warps; slot = by*8 + warp (0..23).
// Lane holds elements i and i+32 — the rotate_half partners — so RoPE is local.
__global__ __launch_bounds__(256)
void qkrope_kernel(const __half* __restrict__ qkv, const float* __restrict__ qn_w,
                   const float* __restrict__ kn_w, const float2* __restrict__ rope,
                   __half* __restrict__ Qo, __half* __restrict__ Ko,
                   __half* __restrict__ Vo)
{
    int t    = blockIdx.x;             // token = s*BATCH + b
    int wid  = threadIdx.x >> 5;
    int lane = threadIdx.x & 31;
    int slot = blockIdx.y * 8 + wid;   // 0..23
    int s = t / BATCH, b = t % BATCH;

    if (slot >= 20) {   // V: copy 64 halves (one unsigned per lane)
        int vh = slot - 20;
        const unsigned* src = (const unsigned*)(qkv + (size_t)t * QKVN + 1280 + vh * 64);
        unsigned* dst = (unsigned*)(Vo + ((size_t)(b * NKV + vh) * S_LEN + s) * 64);
        dst[lane] = src[lane];
        return;
    }

    bool is_q = (slot < 16);
    int base = is_q ? slot * 64 : 1024 + (slot - 16) * 64;
    const __half* src = qkv + (size_t)t * QKVN + base;
    float v0 = __half2float(src[lane]);
    float v1 = __half2float(src[lane + 32]);
    float ss = v0 * v0 + v1 * v1;
    #pragma unroll
    for (int off = 16; off; off >>= 1) ss += __shfl_xor_sync(0xffffffffu, ss, off);
    float sc = rsqrtf(ss * (1.0f / 64.0f) + EPS_F);
    const float* w = is_q ? qn_w : kn_w;
    float nv0 = v0 * sc * w[lane];
    float nv1 = v1 * sc * w[lane + 32];
    float2 cs2 = rope[(size_t)s * 32 + lane];
    float out0 = nv0 * cs2.x - nv1 * cs2.y;
    float out1 = nv1 * cs2.x + nv0 * cs2.y;
    if (is_q) {
        out0 *= QK_SCALE;
        out1 *= QK_SCALE;
        __half* dst = Qo + ((size_t)(b * NHEAD + slot) * S_LEN + s) * 64;
        dst[lane]      = __float2half_rn(out0);
        dst[lane + 32] = __float2half_rn(out1);
    } else {
        __half* dst = Ko + ((size_t)(b * NKV + (slot - 16)) * S_LEN + s) * 64;
        dst[lane]      = __float2half_rn(out0);
        dst[lane + 32] = __float2half_rn(out1);
    }
}

// ---------------- fp16 GEMM stage loader: 8 cp.async per thread ----------------
__device__ __forceinline__ void gf_load(uint32_t sA, uint32_t sB,
                                        const __half* Ag, const __half* Bg,
                                        int K, int k0, int tid)
{
    int r0 = tid >> 2;             // 0..31
    int ch = (tid & 3) << 3;       // half offset in row: 0,8,16,24
    #pragma unroll
    for (int j = 0; j < 4; j++) {
        int r = r0 + 32 * j;
        uint32_t so = (uint32_t)(r * 80 + ch * 2);
        cp16s(sA + so, Ag + (size_t)r * K + k0 + ch);
        cp16s(sB + so, Bg + (size_t)r * K + k0 + ch);
    }
    asm volatile("cp.async.commit_group;" ::: "memory");
}

// ---------------- fp16 GEMM ----------------
// EPI: 1 = gelu(+bias) fp16 out, 2 = +bias+residual fp32 out, 3 = +bias fp16 out
template<int EPI>
__global__ __launch_bounds__(128)
void gemm_f16_kernel(const __half* __restrict__ A, const __half* __restrict__ Bt,
                     const float* __restrict__ bias, const float* __restrict__ res,
                     void* __restrict__ Cout, int M, int N, int K)
{
    extern __shared__ char smc[];
    uint32_t smem_base;
    asm("{ .reg .u64 t; cvta.to.shared.u64 t, %1; cvt.u32.u64 %0, t; }"
        : "=r"(smem_base) : "l"(smc));

    int tid  = threadIdx.x;
    int wid  = tid >> 5, lane = tid & 31;
    int g    = lane >> 2;
    int q    = lane & 3;
    int wm   = (wid >> 1) * 64;
    int wn   = (wid & 1) * 64;

    int row0 = blockIdx.y * 128;
    int col0 = blockIdx.x * 128;
    const __half* Ag = A  + (size_t)row0 * K;
    const __half* Bg = Bt + (size_t)col0 * K;

    float acc[4][8][4];
    #pragma unroll
    for (int mt = 0; mt < 4; mt++)
        #pragma unroll
        for (int nt = 0; nt < 8; nt++)
            #pragma unroll
            for (int r = 0; r < 4; r++) acc[mt][nt][r] = 0.f;

    const int KT = K >> 5;

    #pragma unroll
    for (int st = 0; st < 3; st++)
        gf_load(smem_base + st * GF_TILE_BYTES,
                smem_base + (GF_STAGES + st) * GF_TILE_BYTES,
                Ag, Bg, K, st * 32, tid);

    for (int kt = 0; kt < KT; kt++) {
        asm volatile("cp.async.wait_group 2;" ::: "memory");
        __syncthreads();

        if (kt + 3 < KT) {
            int st = (kt + 3) & 3;
            gf_load(smem_base + st * GF_TILE_BYTES,
                    smem_base + (GF_STAGES + st) * GF_TILE_BYTES,
                    Ag, Bg, K, (kt + 3) * 32, tid);
        }

        int st = kt & 3;
        const __half* As = (const __half*)(smc + st * GF_TILE_BYTES);
        const __half* Bs = (const __half*)(smc + (GF_STAGES + st) * GF_TILE_BYTES);

        #pragma unroll
        for (int kk = 0; kk < 32; kk += 16) {
            unsigned af[4][4];
            #pragma unroll
            for (int mt = 0; mt < 4; mt++) {
                int r = wm + mt * 16 + g;
                af[mt][0] = *(const unsigned*)(As + r * 40 + kk + 2 * q);
                af[mt][1] = *(const unsigned*)(As + (r + 8) * 40 + kk + 2 * q);
                af[mt][2] = *(const unsigned*)(As + r * 40 + kk + 2 * q + 8);
                af[mt][3] = *(const unsigned*)(As + (r + 8) * 40 + kk + 2 * q + 8);
            }
            unsigned bf[8][2];
            #pragma unroll
            for (int nt = 0; nt < 8; nt++) {
                int c = wn + nt * 8 + g;
                bf[nt][0] = *(const unsigned*)(Bs + c * 40 + kk + 2 * q);
                bf[nt][1] = *(const unsigned*)(Bs + c * 40 + kk + 2 * q + 8);
            }
            #pragma unroll
            for (int mt = 0; mt < 4; mt++)
                #pragma unroll
                for (int nt = 0; nt < 8; nt++) {
                    asm volatile(
                        "mma.sync.aligned.m16n8k16.row.col.f32.f16.f16.f32 "
                        "{%0,%1,%2,%3}, {%4,%5,%6,%7}, {%8,%9}, {%0,%1,%2,%3};"
                        : "+f"(acc[mt][nt][0]), "+f"(acc[mt][nt][1]),
                          "+f"(acc[mt][nt][2]), "+f"(acc[mt][nt][3])
                        : "r"(af[mt][0]), "r"(af[mt][1]), "r"(af[mt][2]), "r"(af[mt][3]),
                          "r"(bf[nt][0]), "r"(bf[nt][1]));
                }
        }
    }

    #pragma unroll
    for (int mt = 0; mt < 4; mt++) {
        int r = row0 + wm + mt * 16 + g;
        #pragma unroll
        for (int nt = 0; nt < 8; nt++) {
            int c = col0 + wn + nt * 8 + 2 * q;
            float bv0 = bias[c], bv1 = bias[c + 1];
            float v00 = acc[mt][nt][0] + bv0;
            float v01 = acc[mt][nt][1] + bv1;
            float v10 = acc[mt][nt][2] + bv0;
            float v11 = acc[mt][nt][3] + bv1;
            if (EPI == 1) {
                v00 = 0.5f * v00 * (1.0f + erff(v00 * 0.70710678118654752f));
                v01 = 0.5f * v01 * (1.0f + erff(v01 * 0.70710678118654752f));
                v10 = 0.5f * v10 * (1.0f + erff(v10 * 0.70710678118654752f));
                v11 = 0.5f * v11 * (1.0f + erff(v11 * 0.70710678118654752f));
            }
            if (EPI == 1 || EPI == 3) {
                __half* C = (__half*)Cout;
                *(unsigned*)(C + (size_t)r * N + c)       = packh2(v00, v01);
                *(unsigned*)(C + (size_t)(r + 8) * N + c) = packh2(v10, v11);
            } else {
                float* C = (float*)Cout;
                if (EPI == 2) {
                    float2 r0 = *(const float2*)(res + (size_t)r * N + c);
                    float2 r1 = *(const float2*)(res + (size_t)(r + 8) * N + c);
                    v00 += r0.x; v01 += r0.y;
                    v10 += r1.x; v11 += r1.y;
                }
                *(float2*)(C + (size_t)r * N + c)       = make_float2(v00, v01);
                *(float2*)(C + (size_t)(r + 8) * N + c) = make_float2(v10, v11);
            }
        }
    }
}

// ---------------- fp16 flash attention: BQ=128, 8 warps, single-buffer K/V -----------
__global__ __launch_bounds__(256)
void attn_f16_kernel(const __half* __restrict__ Q, const __half* __restrict__ K,
                     const __half* __restrict__ V, __half* __restrict__ O)
{
    __shared__ __half Qs[128][72];
    __shared__ __half Ks[64][72];
    __shared__ __half Vs[64][72];

    int tid  = threadIdx.x;
    int wid  = tid >> 5, lane = tid & 31;
    int g    = lane >> 2;
    int q    = lane & 3;
    int qt   = gridDim.x - 1 - blockIdx.x;   // longest-job-first
    int bh   = blockIdx.y;
    int b    = bh >> 4;
    int h    = bh & 15;
    int kvh  = h >> 2;
    int q0   = qt * 128;

    const __half* Qb = Q + (size_t)(b * NHEAD + h)  * S_LEN * 64 + (size_t)q0 * 64;
    const __half* Kb = K + (size_t)(b * NKV  + kvh) * S_LEN * 64;
    const __half* Vb = V + (size_t)(b * NKV  + kvh) * S_LEN * 64;

    for (int i = tid; i < 128 * 8; i += 256) {
        int r = i >> 3, c = (i & 7) * 8;
        *(uint4*)&Qs[r][c] = *(const uint4*)(Qb + (size_t)r * 64 + c);
    }
    __syncthreads();

    int row_a = 16 * wid + g;      // 0..127
    int grow = q0 + row_a;
    unsigned qa[4][4];
    #pragma unroll
    for (int c4 = 0; c4 < 4; c4++) {
        int kk = c4 * 16;
        qa[c4][0] = *(const unsigned*)&Qs[row_a][kk + 2 * q];
        qa[c4][1] = *(const unsigned*)&Qs[row_a + 8][kk + 2 * q];
        qa[c4][2] = *(const unsigned*)&Qs[row_a][kk + 2 * q + 8];
        qa[c4][3] = *(const unsigned*)&Qs[row_a + 8][kk + 2 * q + 8];
    }

    float m0 = -INFINITY, m1 = -INFINITY, l0 = 0.f, l1 = 0.f;
    float o[8][4];
    #pragma unroll
    for (int nt = 0; nt < 8; nt++)
        #pragma unroll
        for (int r = 0; r < 4; r++) o[nt][r] = 0.f;

    int nkt = 2 * qt + 2;
    int vmat = lane >> 3;
    int vrow = lane & 7;

    for (int jt = 0; jt < nkt; ++jt) {
        int j0 = jt * 64;
        __syncthreads();
        for (int i = tid; i < 64 * 8; i += 256) {
            int r = i >> 3, c = (i & 7) * 8;
            *(uint4*)&Ks[r][c] = *(const uint4*)(Kb + (size_t)(j0 + r) * 64 + c);
            *(uint4*)&Vs[r][c] = *(const uint4*)(Vb + (size_t)(j0 + r) * 64 + c);
        }
        __syncthreads();

        if (j0 > grow + 8) continue;

        float s[8][4];
        #pragma unroll
        for (int nt = 0; nt < 8; nt++)
            #pragma unroll
            for (int r = 0; r < 4; r++) s[nt][r] = 0.f;

        #pragma unroll
        for (int c4 = 0; c4 < 4; c4++) {
            int kk = c4 * 16;
            #pragma unroll
            for (int nt = 0; nt < 8; nt++) {
                unsigned b0 = *(const unsigned*)&Ks[nt * 8 + g][kk + 2 * q];
                unsigned b1 = *(const unsigned*)&Ks[nt * 8 + g][kk + 2 * q + 8];
                asm volatile(
                    "mma.sync.aligned.m16n8k16.row.col.f32.f16.f16.f32 "
                    "{%0,%1,%2,%3}, {%4,%5,%6,%7}, {%8,%9}, {%0,%1,%2,%3};"
                    : "+f"(s[nt][0]), "+f"(s[nt][1]), "+f"(s[nt][2]), "+f"(s[nt][3])
                    : "r"(qa[c4][0]), "r"(qa[c4][1]), "r"(qa[c4][2]), "r"(qa[c4][3]),
                      "r"(b0), "r"(b1));
            }
        }

        if (j0 + 63 > grow) {
            #pragma unroll
            for (int nt = 0; nt < 8; nt++) {
                int colg = j0 + nt * 8 + 2 * q;
                if (colg     > grow)     s[nt][0] = -INFINITY;
                if (colg + 1 > grow)     s[nt][1] = -INFINITY;
                if (colg     > grow + 8) s[nt][2] = -INFINITY;
                if (colg + 1 > grow + 8) s[nt][3] = -INFINITY;
            }
        }

        float mt0 = -INFINITY, mt1 = -INFINITY;
        #pragma unroll
        for (int nt = 0; nt < 8; nt++) {
            mt0 = fmaxf(mt0, fmaxf(s[nt][0], s[nt][1]));
            mt1 = fmaxf(mt1, fmaxf(s[nt][2], s[nt][3]));
        }
        #pragma unroll
        for (int off = 1; off < 4; off <<= 1) {
            mt0 = fmaxf(mt0, __shfl_xor_sync(0xffffffffu, mt0, off));
            mt1 = fmaxf(mt1, __shfl_xor_sync(0xffffffffu, mt1, off));
        }
        float mn0 = fmaxf(m0, mt0), mn1 = fmaxf(m1, mt1);
        float al0 = __expf(m0 - mn0), al1 = __expf(m1 - mn1);
        m0 = mn0; m1 = mn1;
        float ps0 = 0.f, ps1 = 0.f;
        #pragma unroll
        for (int nt = 0; nt < 8; nt++) {
            s[nt][0] = __expf(s[nt][0] - mn0);
            s[nt][1] = __expf(s[nt][1] - mn0);
            s[nt][2] = __expf(s[nt][2] - mn1);
            s[nt][3] = __expf(s[nt][3] - mn1);
            ps0 += s[nt][0] + s[nt][1];
            ps1 += s[nt][2] + s[nt][3];
            o[nt][0] *= al0; o[nt][1] *= al0;
            o[nt][2] *= al1; o[nt][3] *= al1;
        }
        #pragma unroll
        for (int off = 1; off < 4; off <<= 1) {
            ps0 += __shfl_xor_sync(0xffffffffu, ps0, off);
            ps1 += __shfl_xor_sync(0xffffffffu, ps1, off);
        }
        l0 = l0 * al0 + ps0;
        l1 = l1 * al1 + ps1;

        #pragma unroll
        for (int kc = 0; kc < 4; kc++) {
            unsigned a0 = packh2(s[2 * kc][0],     s[2 * kc][1]);
            unsigned a1 = packh2(s[2 * kc][2],     s[2 * kc][3]);
            unsigned a2 = packh2(s[2 * kc + 1][0], s[2 * kc + 1][1]);
            unsigned a3 = packh2(s[2 * kc + 1][2], s[2 * kc + 1][3]);
            #pragma unroll
            for (int ntp = 0; ntp < 4; ntp++) {
                const __half* vp = &Vs[kc * 16 + (vmat & 1) * 8 + vrow]
                                      [ntp * 16 + (vmat >> 1) * 8];
                uint32_t vaddr = (uint32_t)__cvta_generic_to_shared(vp);
                unsigned v0, v1, v2, v3;
                asm volatile(
                    "ldmatrix.sync.aligned.m8n8.x4.trans.shared.b16 {%0,%1,%2,%3}, [%4];"
                    : "=r"(v0), "=r"(v1), "=r"(v2), "=r"(v3) : "r"(vaddr));
                asm volatile(
                    "mma.sync.aligned.m16n8k16.row.col.f32.f16.f16.f32 "
                    "{%0,%1,%2,%3}, {%4,%5,%6,%7}, {%8,%9}, {%0,%1,%2,%3};"
                    : "+f"(o[2 * ntp][0]), "+f"(o[2 * ntp][1]),
                      "+f"(o[2 * ntp][2]), "+f"(o[2 * ntp][3])
                    : "r"(a0), "r"(a1), "r"(a2), "r"(a3), "r"(v0), "r"(v1));
                asm volatile(
                    "mma.sync.aligned.m16n8k16.row.col.f32.f16.f16.f32 "
                    "{%0,%1,%2,%3}, {%4,%5,%6,%7}, {%8,%9}, {%0,%1,%2,%3};"
                    : "+f"(o[2 * ntp + 1][0]), "+f"(o[2 * ntp + 1][1]),
                      "+f"(o[2 * ntp + 1][2]), "+f"(o[2 * ntp + 1][3])
                    : "r"(a0), "r"(a1), "r"(a2), "r"(a3), "r"(v2), "r"(v3));
            }
        }
    }

    float inv0 = 1.0f / l0, inv1 = 1.0f / l1;
    int srow0 = q0 + row_a;
    int srow1 = srow0 + 8;
    #pragma unroll
    for (int nt = 0; nt < 8; nt++) {
        int c = h * 64 + nt * 8 + 2 * q;
        *(unsigned*)(O + ((size_t)srow0 * BATCH + b) * DMODEL + c) =
            packh2(o[nt][0] * inv0, o[nt][1] * inv0);
        *(unsigned*)(O + ((size_t)srow1 * BATCH + b) * DMODEL + c) =
            packh2(o[nt][2] * inv1, o[nt][3] * inv1);
    }
}

// ---------------- host orchestration ----------------
extern "C" void kernel_launch(void* const* d_in, const int* in_sizes, int n_in,
                              void* d_out, int out_size)
{
    const float* x   = (const float*)d_in[0];
    const float* n1w = (const float*)d_in[1];
    const float* wq  = (const float*)d_in[2];
    const float* bq  = (const float*)d_in[3];
    const float* wk  = (const float*)d_in[4];
    const float* bk  = (const float*)d_in[5];
    const float* wv  = (const float*)d_in[6];
    const float* bv  = (const float*)d_in[7];
    const float* qnw = (const float*)d_in[8];
    const float* knw = (const float*)d_in[9];
    const float* wo  = (const float*)d_in[10];
    const float* bo  = (const float*)d_in[11];
    const float* n2w = (const float*)d_in[12];
    const float* w1  = (const float*)d_in[13];
    const float* b1  = (const float*)d_in[14];
    const float* w2  = (const float*)d_in[15];
    const float* b2  = (const float*)d_in[16];

    __half *ph, *pwqkv, *pqkv, *pattn, *ph2, *pmid, *pwor, *pw1r, *pw2r, *pq, *pk, *pv;
    float *pbqkv, *px1;
    float2* prope;
    cudaGetSymbolAddress((void**)&ph,    g_h);
    cudaGetSymbolAddress((void**)&pwqkv, g_wqkv);
    cudaGetSymbolAddress((void**)&pbqkv, g_bqkv);
    cudaGetSymbolAddress((void**)&pqkv,  g_qkv);
    cudaGetSymbolAddress((void**)&pq,    g_q);
    cudaGetSymbolAddress((void**)&pk,    g_k);
    cudaGetSymbolAddress((void**)&pv,    g_v);
    cudaGetSymbolAddress((void**)&pattn, g_attn);
    cudaGetSymbolAddress((void**)&px1,   g_x1);
    cudaGetSymbolAddress((void**)&ph2,   g_h2);
    cudaGetSymbolAddress((void**)&pmid,  g_mid);
    cudaGetSymbolAddress((void**)&pwor,  g_wor);
    cudaGetSymbolAddress((void**)&pw1r,  g_w1r);
    cudaGetSymbolAddress((void**)&pw2r,  g_w2r);
    cudaGetSymbolAddress((void**)&prope, g_rope);

    cudaFuncSetAttribute(gemm_f16_kernel<1>,
                         cudaFuncAttributeMaxDynamicSharedMemorySize, GF_SMEM_BYTES);
    cudaFuncSetAttribute(gemm_f16_kernel<2>,
                         cudaFuncAttributeMaxDynamicSharedMemorySize, GF_SMEM_BYTES);
    cudaFuncSetAttribute(gemm_f16_kernel<3>,
                         cudaFuncAttributeMaxDynamicSharedMemorySize, GF_SMEM_BYTES);

    prep_kernel<<<PREP_TOTAL, 256>>>(wq, wk, wv, bq, bk, bv, wo, w1, w2,
                                     pwqkv, pbqkv, pwor, pw1r, pw2r, prope);

    rmsnorm_kernel<<<NTOK / 8, 256>>>(x, n1w, ph);
    gemm_f16_kernel<3><<<dim3(QKVN / 128, NTOK / 128), 128, GF_SMEM_BYTES>>>(
        ph, pwqkv, pbqkv, nullptr, pqkv, NTOK, QKVN, DMODEL);
    qkrope_kernel<<<dim3(NTOK, 3), 256>>>(pqkv, qnw, knw, prope, pq, pk, pv);
    attn_f16_kernel<<<dim3(S_LEN / 128, BATCH * NHEAD), 256>>>(pq, pk, pv, pattn);
    gemm_f16_kernel<2><<<dim3(DMODEL / 128, NTOK / 128), 128, GF_SMEM_BYTES>>>(
        pattn, pwor, bo, x, px1, NTOK, DMODEL, DMODEL);
    rmsnorm_kernel<<<NTOK / 8, 256>>>(px1, n2w, ph2);
    gemm_f16_kernel<1><<<dim3(DFF / 128, NTOK / 128), 128, GF_SMEM_BYTES>>>(
        ph2, pw1r, b1, nullptr, pmid, NTOK, DFF, DMODEL);
    gemm_f16_kernel<2><<<dim3(DMODEL / 128, NTOK / 128), 128, GF_SMEM_BYTES>>>(
        pmid, pw2r, b2, px1, d_out, NTOK, DMODEL, DFF);
}